// round 1
// baseline (speedup 1.0000x reference)
#include <cuda_runtime.h>
#include <math.h>

#define T_ 256
#define S_ 128
#define B_ 32
#define H_ 1024
#define NH_ 16
#define D_ 64
#define F_ 4096

// ---------------- scratch (static device globals; no allocation) ----------------
__device__ float g_q[(size_t)T_ * B_ * H_];
__device__ float g_k[(size_t)S_ * B_ * H_];
__device__ float g_v[(size_t)S_ * B_ * H_];
__device__ float g_ctx[(size_t)T_ * B_ * H_];
__device__ float g_attn[(size_t)T_ * B_ * H_];
__device__ float g_ffnh[(size_t)T_ * B_ * F_];
__device__ float g_ffnx[(size_t)T_ * B_ * H_];
__device__ float g_gpre[(size_t)T_ * B_ * 4 * H_];
__device__ float g_hbuf[2 * B_ * H_];
__device__ float g_cbuf[B_ * H_];

// ---------------- generic fp32 GEMM: C = A[MxK] @ B[KxN](ldb) (+bias)(+relu)(+=C) ----
// flags: 1 = add bias[N], 2 = relu, 4 = accumulate into existing C
__global__ __launch_bounds__(256, 2)
void sgemm_kernel(const float* __restrict__ A, const float* __restrict__ Bm,
                  const float* __restrict__ bias, float* __restrict__ C,
                  int M, int N, int K, int ldb, int flags)
{
    __shared__ float As[128][17];
    __shared__ float Bs[16][128];
    const int tid = threadIdx.x;
    const int tx = tid & 15;
    const int ty = tid >> 4;
    const int m0 = blockIdx.y * 128;
    const int n0 = blockIdx.x * 128;

    const int arow = tid >> 2;          // 0..63
    const int acol = (tid & 3) << 2;    // 0,4,8,12
    const int brow = tid >> 5;          // 0..7
    const int bcol = (tid & 31) << 2;   // 0..124

    float acc[8][8];
#pragma unroll
    for (int i = 0; i < 8; i++)
#pragma unroll
        for (int j = 0; j < 8; j++) acc[i][j] = 0.f;

    const float* Ap0 = A + (size_t)(m0 + arow) * K + acol;
    const float* Ap1 = A + (size_t)(m0 + arow + 64) * K + acol;
    const float* Bp0 = Bm + (size_t)brow * ldb + n0 + bcol;
    const float* Bp1 = Bm + (size_t)(brow + 8) * ldb + n0 + bcol;

    // prefetch tile 0
    float4 pa0 = *(const float4*)Ap0;
    float4 pa1 = *(const float4*)Ap1;
    float4 pb0 = *(const float4*)Bp0;
    float4 pb1 = *(const float4*)Bp1;

    const int ktiles = K >> 4;
    for (int kt = 0; kt < ktiles; kt++) {
        As[arow][acol + 0] = pa0.x; As[arow][acol + 1] = pa0.y;
        As[arow][acol + 2] = pa0.z; As[arow][acol + 3] = pa0.w;
        As[arow + 64][acol + 0] = pa1.x; As[arow + 64][acol + 1] = pa1.y;
        As[arow + 64][acol + 2] = pa1.z; As[arow + 64][acol + 3] = pa1.w;
        *(float4*)&Bs[brow][bcol] = pb0;
        *(float4*)&Bs[brow + 8][bcol] = pb1;
        __syncthreads();

        if (kt + 1 < ktiles) {  // prefetch next tile while computing this one
            pa0 = *(const float4*)(Ap0 + (kt + 1) * 16);
            pa1 = *(const float4*)(Ap1 + (kt + 1) * 16);
            pb0 = *(const float4*)(Bp0 + (size_t)(kt + 1) * 16 * ldb);
            pb1 = *(const float4*)(Bp1 + (size_t)(kt + 1) * 16 * ldb);
        }

#pragma unroll
        for (int kk = 0; kk < 16; kk++) {
            float a[8], b[8];
#pragma unroll
            for (int i = 0; i < 8; i++) a[i] = As[ty * 8 + i][kk];
            float4 b0 = *(const float4*)&Bs[kk][tx * 4];
            float4 b1 = *(const float4*)&Bs[kk][64 + tx * 4];
            b[0] = b0.x; b[1] = b0.y; b[2] = b0.z; b[3] = b0.w;
            b[4] = b1.x; b[5] = b1.y; b[6] = b1.z; b[7] = b1.w;
#pragma unroll
            for (int i = 0; i < 8; i++)
#pragma unroll
                for (int j = 0; j < 8; j++)
                    acc[i][j] = fmaf(a[i], b[j], acc[i][j]);
        }
        __syncthreads();
    }

    // epilogue: thread cols = n0 + tx*4 + {0..3} and n0 + 64 + tx*4 + {0..3}
#pragma unroll
    for (int i = 0; i < 8; i++) {
        int m = m0 + ty * 8 + i;
        float* crow = C + (size_t)m * N + n0;
#pragma unroll
        for (int half = 0; half < 2; half++) {
            int nc = half * 64 + tx * 4;
            float4 v;
            v.x = acc[i][half * 4 + 0]; v.y = acc[i][half * 4 + 1];
            v.z = acc[i][half * 4 + 2]; v.w = acc[i][half * 4 + 3];
            if (flags & 4) {
                float4 c = *(float4*)&crow[nc];
                v.x += c.x; v.y += c.y; v.z += c.z; v.w += c.w;
            }
            if (flags & 1) {
                const float* bp = bias + n0 + nc;
                v.x += bp[0]; v.y += bp[1]; v.z += bp[2]; v.w += bp[3];
            }
            if (flags & 2) {
                v.x = fmaxf(v.x, 0.f); v.y = fmaxf(v.y, 0.f);
                v.z = fmaxf(v.z, 0.f); v.w = fmaxf(v.w, 0.f);
            }
            *(float4*)&crow[nc] = v;
        }
    }
}

// ---------------- attention: per (b,h) block over 64-row t-tile --------------------
// q,k,v,ctx laid out as [tokens, B, H] with head h at cols [h*64, h*64+64)
#define ATT_PAD 68
#define ATT_SMEM_FLOATS ((64 + 128 + 128) * ATT_PAD + 8 * 128)

__global__ __launch_bounds__(256)
void attn_kernel(const float* __restrict__ q, const float* __restrict__ k,
                 const float* __restrict__ v, const float* __restrict__ sbias,
                 float* __restrict__ ctx)
{
    extern __shared__ float sm[];
    float* Qs = sm;                       // 64 x 68
    float* Ks = sm + 64 * ATT_PAD;        // 128 x 68
    float* Vs = Ks + 128 * ATT_PAD;       // 128 x 68
    float* probs = Vs + 128 * ATT_PAD;    // 8 warps x 128

    const int b = blockIdx.x / NH_;
    const int h = blockIdx.x % NH_;
    const int t0 = blockIdx.y * 64;
    const int tid = threadIdx.x;
    const int lane = tid & 31;
    const int warp = tid >> 5;
    const int hd = h * D_;

    for (int e = tid; e < 128 * 16; e += 256) {   // 2048 float4s
        int s = e >> 4;
        int d4 = (e & 15) << 2;
        size_t gofs = ((size_t)(s * B_ + b)) * H_ + hd + d4;
        *(float4*)&Ks[s * ATT_PAD + d4] = *(const float4*)&k[gofs];
        *(float4*)&Vs[s * ATT_PAD + d4] = *(const float4*)&v[gofs];
    }
    for (int e = tid; e < 64 * 16; e += 256) {    // 1024 float4s
        int r = e >> 4;
        int d4 = (e & 15) << 2;
        *(float4*)&Qs[r * ATT_PAD + d4] =
            *(const float4*)&q[((size_t)((t0 + r) * B_ + b)) * H_ + hd + d4];
    }
    __syncthreads();

    const float scale = 0.125f;  // 1/sqrt(64)
    float* pw = probs + warp * 128;

    for (int r8 = 0; r8 < 8; r8++) {
        int row = warp * 8 + r8;
        const float4* qrow = (const float4*)&Qs[row * ATT_PAD];
        const float4* k0p = (const float4*)&Ks[(lane) * ATT_PAD];
        const float4* k1p = (const float4*)&Ks[(lane + 32) * ATT_PAD];
        const float4* k2p = (const float4*)&Ks[(lane + 64) * ATT_PAD];
        const float4* k3p = (const float4*)&Ks[(lane + 96) * ATT_PAD];
        float a0 = 0.f, a1 = 0.f, a2 = 0.f, a3 = 0.f;
#pragma unroll
        for (int d4 = 0; d4 < 16; d4++) {
            float4 qv = qrow[d4];
            float4 kv;
            kv = k0p[d4]; a0 += qv.x*kv.x + qv.y*kv.y + qv.z*kv.z + qv.w*kv.w;
            kv = k1p[d4]; a1 += qv.x*kv.x + qv.y*kv.y + qv.z*kv.z + qv.w*kv.w;
            kv = k2p[d4]; a2 += qv.x*kv.x + qv.y*kv.y + qv.z*kv.z + qv.w*kv.w;
            kv = k3p[d4]; a3 += qv.x*kv.x + qv.y*kv.y + qv.z*kv.z + qv.w*kv.w;
        }
        a0 = a0 * scale + sbias[b * S_ + lane];
        a1 = a1 * scale + sbias[b * S_ + lane + 32];
        a2 = a2 * scale + sbias[b * S_ + lane + 64];
        a3 = a3 * scale + sbias[b * S_ + lane + 96];

        float mx = fmaxf(fmaxf(a0, a1), fmaxf(a2, a3));
#pragma unroll
        for (int off = 16; off; off >>= 1)
            mx = fmaxf(mx, __shfl_xor_sync(0xffffffffu, mx, off));
        float e0 = __expf(a0 - mx), e1 = __expf(a1 - mx);
        float e2 = __expf(a2 - mx), e3 = __expf(a3 - mx);
        float ssum = e0 + e1 + e2 + e3;
#pragma unroll
        for (int off = 16; off; off >>= 1)
            ssum += __shfl_xor_sync(0xffffffffu, ssum, off);
        float inv = 1.f / ssum;

        pw[lane] = e0 * inv; pw[lane + 32] = e1 * inv;
        pw[lane + 64] = e2 * inv; pw[lane + 96] = e3 * inv;
        __syncwarp();

        float c0 = 0.f, c1 = 0.f;
#pragma unroll 4
        for (int s = 0; s < 128; s++) {
            float p = pw[s];
            c0 += p * Vs[s * ATT_PAD + lane];
            c1 += p * Vs[s * ATT_PAD + lane + 32];
        }
        float* crow = &ctx[((size_t)((t0 + row) * B_ + b)) * H_ + hd];
        crow[lane] = c0;
        crow[lane + 32] = c1;
        __syncwarp();
    }
}

// ---------------- LSTM recurrent step ---------------------------------------------
// g[b, :] = gpre[t,b,:] + h @ Whh  (Whh = Wg rows [2H,3H), shape [H, 4H])
// then gates + state update + write hidden. Block owns 8 hidden cols x 4 gates.
__global__ __launch_bounds__(256)
void lstm_step_kernel(const float* __restrict__ gpre_t, const float* __restrict__ Whh,
                      const float* __restrict__ h_in, float* __restrict__ h_out,
                      float* __restrict__ c, float* __restrict__ out_hid,
                      float* __restrict__ cf, float* __restrict__ hf, int last)
{
    __shared__ float hs[32][33];
    __shared__ float Ws[32][33];
    __shared__ float gs[32][32];
    const int tid = threadIdx.x;
    const int c0 = blockIdx.x * 8;
    const int colidx = tid & 31;            // 0..31 = gate*8 + j
    const int rbase = (tid >> 5) * 4;       // 4 batch rows per thread
    const int gcol = (colidx >> 3) * H_ + c0 + (colidx & 7);

    float acc[4];
#pragma unroll
    for (int i = 0; i < 4; i++)
        acc[i] = gpre_t[(size_t)(rbase + i) * (4 * H_) + gcol];

    for (int k0 = 0; k0 < H_; k0 += 32) {
#pragma unroll
        for (int i = 0; i < 4; i++) {
            int e = tid + 256 * i;
            int rr = e >> 5, kk = e & 31;
            hs[rr][kk] = h_in[rr * H_ + k0 + kk];
            int cc = e & 31;
            Ws[rr][cc] = Whh[(size_t)(k0 + rr) * (4 * H_) + (cc >> 3) * H_ + c0 + (cc & 7)];
        }
        __syncthreads();
#pragma unroll
        for (int kk = 0; kk < 32; kk++) {
            float w = Ws[kk][colidx];
#pragma unroll
            for (int i = 0; i < 4; i++)
                acc[i] += hs[rbase + i][kk] * w;
        }
        __syncthreads();
    }
#pragma unroll
    for (int i = 0; i < 4; i++) gs[rbase + i][colidx] = acc[i];
    __syncthreads();

    {
        int row = tid >> 3;       // 0..31 batch
        int jj = tid & 7;
        int hc = c0 + jj;
        float iv = 1.f / (1.f + __expf(-gs[row][jj]));
        float jv = tanhf(gs[row][8 + jj]);
        float fv = 1.f / (1.f + __expf(-gs[row][16 + jj]));
        float ov = 1.f / (1.f + __expf(-gs[row][24 + jj]));
        float cold = c[row * H_ + hc];
        float nc = fv * cold + iv * jv;
        float nh = ov * nc;                 // THUMT LSTMCell: activation=None
        c[row * H_ + hc] = nc;
        h_out[row * H_ + hc] = nh;
        out_hid[row * H_ + hc] = nh;
        if (last) {
            cf[row * H_ + hc] = nc;
            hf[row * H_ + hc] = nh;
        }
    }
}

__global__ void init_state(float* h0, float* cc)
{
    int i = blockIdx.x * 256 + threadIdx.x;
    if (i < B_ * H_) { h0[i] = 0.f; cc[i] = 0.f; }
}

// ---------------- launch ------------------------------------------------------------
extern "C" void kernel_launch(void* const* d_in, const int* in_sizes, int n_in,
                              void* d_out, int out_size)
{
    (void)in_sizes; (void)n_in;
    const float* x  = (const float*)d_in[0];
    const float* sb = (const float*)d_in[1];
    // d_in[2] = tgt_bias (unused by reference)
    const float* mem = (const float*)d_in[3];
    const float* Wq = (const float*)d_in[4];  const float* bq = (const float*)d_in[5];
    const float* Wk = (const float*)d_in[6];  const float* bk = (const float*)d_in[7];
    const float* Wv = (const float*)d_in[8];  const float* bv = (const float*)d_in[9];
    const float* Wo = (const float*)d_in[10]; const float* bo = (const float*)d_in[11];
    const float* W1 = (const float*)d_in[12]; const float* b1 = (const float*)d_in[13];
    const float* W2 = (const float*)d_in[14]; const float* b2 = (const float*)d_in[15];
    const float* Wg = (const float*)d_in[16]; const float* bg = (const float*)d_in[17];
    float* out = (float*)d_out;

    float *q, *k, *v, *ctx, *attn, *ffnh, *ffnx, *gpre, *hbuf, *cbuf;
    cudaGetSymbolAddress((void**)&q,    g_q);
    cudaGetSymbolAddress((void**)&k,    g_k);
    cudaGetSymbolAddress((void**)&v,    g_v);
    cudaGetSymbolAddress((void**)&ctx,  g_ctx);
    cudaGetSymbolAddress((void**)&attn, g_attn);
    cudaGetSymbolAddress((void**)&ffnh, g_ffnh);
    cudaGetSymbolAddress((void**)&ffnx, g_ffnx);
    cudaGetSymbolAddress((void**)&gpre, g_gpre);
    cudaGetSymbolAddress((void**)&hbuf, g_hbuf);
    cudaGetSymbolAddress((void**)&cbuf, g_cbuf);

    dim3 blk(256);

    // projections
    sgemm_kernel<<<dim3(H_ / 128, (T_ * B_) / 128), blk>>>(x,   Wq, bq, q, T_ * B_, H_, H_, H_, 1);
    sgemm_kernel<<<dim3(H_ / 128, (S_ * B_) / 128), blk>>>(mem, Wk, bk, k, S_ * B_, H_, H_, H_, 1);
    sgemm_kernel<<<dim3(H_ / 128, (S_ * B_) / 128), blk>>>(mem, Wv, bv, v, S_ * B_, H_, H_, H_, 1);

    // attention
    size_t attn_smem = (size_t)ATT_SMEM_FLOATS * sizeof(float);
    cudaFuncSetAttribute(attn_kernel, cudaFuncAttributeMaxDynamicSharedMemorySize, (int)attn_smem);
    attn_kernel<<<dim3(B_ * NH_, T_ / 64), blk, attn_smem>>>(q, k, v, sb, ctx);

    // output projection
    sgemm_kernel<<<dim3(H_ / 128, (T_ * B_) / 128), blk>>>(ctx, Wo, bo, attn, T_ * B_, H_, H_, H_, 1);

    // feed-forward
    sgemm_kernel<<<dim3(F_ / 128, (T_ * B_) / 128), blk>>>(x,    W1, b1, ffnh, T_ * B_, F_, H_, F_, 3);
    sgemm_kernel<<<dim3(H_ / 128, (T_ * B_) / 128), blk>>>(ffnh, W2, b2, ffnx, T_ * B_, H_, F_, H_, 1);

    // gate precompute: gpre = ffnx @ Wg[0:H] + attn @ Wg[H:2H] + bg
    sgemm_kernel<<<dim3((4 * H_) / 128, (T_ * B_) / 128), blk>>>(
        ffnx, Wg, bg, gpre, T_ * B_, 4 * H_, H_, 4 * H_, 1);
    sgemm_kernel<<<dim3((4 * H_) / 128, (T_ * B_) / 128), blk>>>(
        attn, Wg + (size_t)H_ * 4 * H_, nullptr, gpre, T_ * B_, 4 * H_, H_, 4 * H_, 4);

    // recurrence
    init_state<<<(B_ * H_ + 255) / 256, 256>>>(hbuf, cbuf);
    const float* Whh = Wg + (size_t)2 * H_ * 4 * H_;
    int has_tail = out_size >= T_ * B_ * H_ + 2 * B_ * H_;
    float* cf = out + (size_t)T_ * B_ * H_;
    float* hf = cf + B_ * H_;
    for (int t = 0; t < T_; t++) {
        lstm_step_kernel<<<H_ / 8, 256>>>(
            gpre + (size_t)t * B_ * 4 * H_, Whh,
            hbuf + (t & 1) * (B_ * H_), hbuf + ((t + 1) & 1) * (B_ * H_), cbuf,
            out + (size_t)t * B_ * H_, cf, hf,
            (t == T_ - 1 && has_tail) ? 1 : 0);
    }
}

// round 2
// speedup vs baseline: 1.6026x; 1.6026x over previous
#include <cuda_runtime.h>
#include <math.h>
#include <stdint.h>

#define T_ 256
#define S_ 128
#define B_ 32
#define H_ 1024
#define NH_ 16
#define D_ 64
#define F_ 4096

// ---------------- scratch (static device globals; no allocation) ----------------
__device__ float g_q[(size_t)T_ * B_ * H_];
__device__ float g_k[(size_t)S_ * B_ * H_];
__device__ float g_v[(size_t)S_ * B_ * H_];
__device__ float g_ctx[(size_t)T_ * B_ * H_];
__device__ float g_attn[(size_t)T_ * B_ * H_];
__device__ float g_ffnh[(size_t)T_ * B_ * F_];
__device__ float g_ffnx[(size_t)T_ * B_ * H_];
__device__ float g_gpre[(size_t)T_ * B_ * 4 * H_];
__device__ float g_hbuf[2 * B_ * H_];
__device__ float g_cbuf[B_ * H_];

// ---------------- tf32 tensor-core GEMM -----------------------------------------
// C[MxN] = A[MxK] @ B[KxN] (B row-major with leading dim ldb)
// flags: 1 = add bias[N], 2 = relu, 4 = accumulate into existing C
// Block tile 128x128x16, 256 threads (8 warps), warp tile 64x32 via m16n8k8 tf32.

__device__ __forceinline__ uint32_t f2tf32(float x) {
    uint32_t u;
    asm("cvt.rna.tf32.f32 %0, %1;" : "=r"(u) : "f"(x));
    return u;
}

__device__ __forceinline__ void mma_tf32(float (&d)[4], const uint32_t (&a)[4],
                                         const uint32_t (&b)[2]) {
    asm volatile(
        "mma.sync.aligned.m16n8k8.row.col.f32.tf32.tf32.f32 "
        "{%0,%1,%2,%3}, {%4,%5,%6,%7}, {%8,%9}, {%0,%1,%2,%3};\n"
        : "+f"(d[0]), "+f"(d[1]), "+f"(d[2]), "+f"(d[3])
        : "r"(a[0]), "r"(a[1]), "r"(a[2]), "r"(a[3]), "r"(b[0]), "r"(b[1]));
}

#define SMS 136   // smem row stride (128 + 8): makes all fragment LDS conflict-free

__global__ __launch_bounds__(256, 2)
void mma_gemm(const float* __restrict__ A, const float* __restrict__ Bm,
              const float* __restrict__ bias, float* __restrict__ C,
              int M, int N, int K, int ldb, int flags)
{
    __shared__ uint32_t As[16][SMS];   // [k][m]  (A transposed into smem)
    __shared__ uint32_t Bs[16][SMS];   // [k][n]

    const int tid  = threadIdx.x;
    const int lane = tid & 31;
    const int warp = tid >> 5;
    const int wm   = warp >> 2;        // 0..1
    const int wn   = warp & 3;         // 0..3
    const int g    = lane >> 2;        // groupID 0..7
    const int t    = lane & 3;         // threadID_in_group 0..3

    const int m0 = blockIdx.y * 128;
    const int n0 = blockIdx.x * 128;

    // A load mapping: rows tid>>2 (+64), cols (tid&3)*4
    const int am  = tid >> 2;
    const int ak4 = (tid & 3) << 2;
    // B load mapping: rows tid>>5 (+8), cols (tid&31)*4
    const int bk  = tid >> 5;
    const int bn4 = (tid & 31) << 2;

    const float* Ap0 = A + (size_t)(m0 + am) * K + ak4;
    const float* Ap1 = A + (size_t)(m0 + am + 64) * K + ak4;
    const float* Bp0 = Bm + (size_t)bk * ldb + n0 + bn4;
    const float* Bp1 = Bm + (size_t)(bk + 8) * ldb + n0 + bn4;

    float acc[4][4][4];
#pragma unroll
    for (int i = 0; i < 4; i++)
#pragma unroll
        for (int j = 0; j < 4; j++)
#pragma unroll
            for (int r = 0; r < 4; r++) acc[i][j][r] = 0.f;

    float4 pa0 = *(const float4*)Ap0;
    float4 pa1 = *(const float4*)Ap1;
    float4 pb0 = *(const float4*)Bp0;
    float4 pb1 = *(const float4*)Bp1;

    const int ktiles = K >> 4;
    for (int kt = 0; kt < ktiles; kt++) {
        // store A (transpose + tf32 round)
        As[ak4 + 0][am] = f2tf32(pa0.x);
        As[ak4 + 1][am] = f2tf32(pa0.y);
        As[ak4 + 2][am] = f2tf32(pa0.z);
        As[ak4 + 3][am] = f2tf32(pa0.w);
        {
            int am2 = am + 64;
            As[ak4 + 0][am2] = f2tf32(pa1.x);
            As[ak4 + 1][am2] = f2tf32(pa1.y);
            As[ak4 + 2][am2] = f2tf32(pa1.z);
            As[ak4 + 3][am2] = f2tf32(pa1.w);
        }
        // store B (tf32 round)
        Bs[bk][bn4 + 0] = f2tf32(pb0.x);
        Bs[bk][bn4 + 1] = f2tf32(pb0.y);
        Bs[bk][bn4 + 2] = f2tf32(pb0.z);
        Bs[bk][bn4 + 3] = f2tf32(pb0.w);
        Bs[bk + 8][bn4 + 0] = f2tf32(pb1.x);
        Bs[bk + 8][bn4 + 1] = f2tf32(pb1.y);
        Bs[bk + 8][bn4 + 2] = f2tf32(pb1.z);
        Bs[bk + 8][bn4 + 3] = f2tf32(pb1.w);
        __syncthreads();

        if (kt + 1 < ktiles) {   // prefetch next K-tile
            Ap0 += 16; Ap1 += 16;
            Bp0 += (size_t)16 * ldb; Bp1 += (size_t)16 * ldb;
            pa0 = *(const float4*)Ap0;
            pa1 = *(const float4*)Ap1;
            pb0 = *(const float4*)Bp0;
            pb1 = *(const float4*)Bp1;
        }

#pragma unroll
        for (int ks = 0; ks < 16; ks += 8) {
            uint32_t af[4][4], bf[4][2];
#pragma unroll
            for (int mi = 0; mi < 4; mi++) {
                int m = wm * 64 + mi * 16 + g;
                af[mi][0] = As[ks + t][m];
                af[mi][1] = As[ks + t][m + 8];
                af[mi][2] = As[ks + t + 4][m];
                af[mi][3] = As[ks + t + 4][m + 8];
            }
#pragma unroll
            for (int ni = 0; ni < 4; ni++) {
                int n = wn * 32 + ni * 8 + g;
                bf[ni][0] = Bs[ks + t][n];
                bf[ni][1] = Bs[ks + t + 4][n];
            }
#pragma unroll
            for (int mi = 0; mi < 4; mi++)
#pragma unroll
                for (int ni = 0; ni < 4; ni++)
                    mma_tf32(acc[mi][ni], af[mi], bf[ni]);
        }
        __syncthreads();
    }

    // epilogue: c0=(g, 2t) c1=(g, 2t+1) c2=(g+8, 2t) c3=(g+8, 2t+1)
#pragma unroll
    for (int mi = 0; mi < 4; mi++) {
#pragma unroll
        for (int ni = 0; ni < 4; ni++) {
            int r0 = m0 + wm * 64 + mi * 16 + g;
            int cc = n0 + wn * 32 + ni * 8 + 2 * t;
            float2 v0 = make_float2(acc[mi][ni][0], acc[mi][ni][1]);
            float2 v1 = make_float2(acc[mi][ni][2], acc[mi][ni][3]);
            float* p0 = C + (size_t)r0 * N + cc;
            float* p1 = C + (size_t)(r0 + 8) * N + cc;
            if (flags & 4) {
                float2 o0 = *(float2*)p0;
                float2 o1 = *(float2*)p1;
                v0.x += o0.x; v0.y += o0.y; v1.x += o1.x; v1.y += o1.y;
            }
            if (flags & 1) {
                float2 bb = *(const float2*)(bias + cc);
                v0.x += bb.x; v0.y += bb.y; v1.x += bb.x; v1.y += bb.y;
            }
            if (flags & 2) {
                v0.x = fmaxf(v0.x, 0.f); v0.y = fmaxf(v0.y, 0.f);
                v1.x = fmaxf(v1.x, 0.f); v1.y = fmaxf(v1.y, 0.f);
            }
            *(float2*)p0 = v0;
            *(float2*)p1 = v1;
        }
    }
}

// ---------------- attention: per (b,h) block over 64-row t-tile --------------------
#define ATT_PAD 68
#define ATT_SMEM_FLOATS ((64 + 128 + 128) * ATT_PAD + 8 * 128)

__global__ __launch_bounds__(256)
void attn_kernel(const float* __restrict__ q, const float* __restrict__ k,
                 const float* __restrict__ v, const float* __restrict__ sbias,
                 float* __restrict__ ctx)
{
    extern __shared__ float sm[];
    float* Qs = sm;                       // 64 x 68
    float* Ks = sm + 64 * ATT_PAD;        // 128 x 68
    float* Vs = Ks + 128 * ATT_PAD;       // 128 x 68
    float* probs = Vs + 128 * ATT_PAD;    // 8 warps x 128

    const int b = blockIdx.x / NH_;
    const int h = blockIdx.x % NH_;
    const int t0 = blockIdx.y * 64;
    const int tid = threadIdx.x;
    const int lane = tid & 31;
    const int warp = tid >> 5;
    const int hd = h * D_;

    for (int e = tid; e < 128 * 16; e += 256) {
        int s = e >> 4;
        int d4 = (e & 15) << 2;
        size_t gofs = ((size_t)(s * B_ + b)) * H_ + hd + d4;
        *(float4*)&Ks[s * ATT_PAD + d4] = *(const float4*)&k[gofs];
        *(float4*)&Vs[s * ATT_PAD + d4] = *(const float4*)&v[gofs];
    }
    for (int e = tid; e < 64 * 16; e += 256) {
        int r = e >> 4;
        int d4 = (e & 15) << 2;
        *(float4*)&Qs[r * ATT_PAD + d4] =
            *(const float4*)&q[((size_t)((t0 + r) * B_ + b)) * H_ + hd + d4];
    }
    __syncthreads();

    const float scale = 0.125f;
    float* pw = probs + warp * 128;

    for (int r8 = 0; r8 < 8; r8++) {
        int row = warp * 8 + r8;
        const float4* qrow = (const float4*)&Qs[row * ATT_PAD];
        const float4* k0p = (const float4*)&Ks[(lane) * ATT_PAD];
        const float4* k1p = (const float4*)&Ks[(lane + 32) * ATT_PAD];
        const float4* k2p = (const float4*)&Ks[(lane + 64) * ATT_PAD];
        const float4* k3p = (const float4*)&Ks[(lane + 96) * ATT_PAD];
        float a0 = 0.f, a1 = 0.f, a2 = 0.f, a3 = 0.f;
#pragma unroll
        for (int d4 = 0; d4 < 16; d4++) {
            float4 qv = qrow[d4];
            float4 kv;
            kv = k0p[d4]; a0 += qv.x*kv.x + qv.y*kv.y + qv.z*kv.z + qv.w*kv.w;
            kv = k1p[d4]; a1 += qv.x*kv.x + qv.y*kv.y + qv.z*kv.z + qv.w*kv.w;
            kv = k2p[d4]; a2 += qv.x*kv.x + qv.y*kv.y + qv.z*kv.z + qv.w*kv.w;
            kv = k3p[d4]; a3 += qv.x*kv.x + qv.y*kv.y + qv.z*kv.z + qv.w*kv.w;
        }
        a0 = a0 * scale + sbias[b * S_ + lane];
        a1 = a1 * scale + sbias[b * S_ + lane + 32];
        a2 = a2 * scale + sbias[b * S_ + lane + 64];
        a3 = a3 * scale + sbias[b * S_ + lane + 96];

        float mx = fmaxf(fmaxf(a0, a1), fmaxf(a2, a3));
#pragma unroll
        for (int off = 16; off; off >>= 1)
            mx = fmaxf(mx, __shfl_xor_sync(0xffffffffu, mx, off));
        float e0 = __expf(a0 - mx), e1 = __expf(a1 - mx);
        float e2 = __expf(a2 - mx), e3 = __expf(a3 - mx);
        float ssum = e0 + e1 + e2 + e3;
#pragma unroll
        for (int off = 16; off; off >>= 1)
            ssum += __shfl_xor_sync(0xffffffffu, ssum, off);
        float inv = 1.f / ssum;

        pw[lane] = e0 * inv; pw[lane + 32] = e1 * inv;
        pw[lane + 64] = e2 * inv; pw[lane + 96] = e3 * inv;
        __syncwarp();

        float c0 = 0.f, c1 = 0.f;
#pragma unroll 4
        for (int s = 0; s < 128; s++) {
            float p = pw[s];
            c0 += p * Vs[s * ATT_PAD + lane];
            c1 += p * Vs[s * ATT_PAD + lane + 32];
        }
        float* crow = &ctx[((size_t)((t0 + row) * B_ + b)) * H_ + hd];
        crow[lane] = c0;
        crow[lane + 32] = c1;
        __syncwarp();
    }
}

// ---------------- LSTM recurrent step ---------------------------------------------
__global__ __launch_bounds__(256)
void lstm_step_kernel(const float* __restrict__ gpre_t, const float* __restrict__ Whh,
                      const float* __restrict__ h_in, float* __restrict__ h_out,
                      float* __restrict__ c, float* __restrict__ out_hid,
                      float* __restrict__ cf, float* __restrict__ hf, int last)
{
    __shared__ float hs[32][33];
    __shared__ float Ws[32][33];
    __shared__ float gs[32][32];
    const int tid = threadIdx.x;
    const int c0 = blockIdx.x * 8;
    const int colidx = tid & 31;
    const int rbase = (tid >> 5) * 4;
    const int gcol = (colidx >> 3) * H_ + c0 + (colidx & 7);

    float acc[4];
#pragma unroll
    for (int i = 0; i < 4; i++)
        acc[i] = gpre_t[(size_t)(rbase + i) * (4 * H_) + gcol];

    for (int k0 = 0; k0 < H_; k0 += 32) {
#pragma unroll
        for (int i = 0; i < 4; i++) {
            int e = tid + 256 * i;
            int rr = e >> 5, kk = e & 31;
            hs[rr][kk] = h_in[rr * H_ + k0 + kk];
            int cc = e & 31;
            Ws[rr][cc] = Whh[(size_t)(k0 + rr) * (4 * H_) + (cc >> 3) * H_ + c0 + (cc & 7)];
        }
        __syncthreads();
#pragma unroll
        for (int kk = 0; kk < 32; kk++) {
            float w = Ws[kk][colidx];
#pragma unroll
            for (int i = 0; i < 4; i++)
                acc[i] += hs[rbase + i][kk] * w;
        }
        __syncthreads();
    }
#pragma unroll
    for (int i = 0; i < 4; i++) gs[rbase + i][colidx] = acc[i];
    __syncthreads();

    {
        int row = tid >> 3;
        int jj = tid & 7;
        int hc = c0 + jj;
        float iv = 1.f / (1.f + __expf(-gs[row][jj]));
        float jv = tanhf(gs[row][8 + jj]);
        float fv = 1.f / (1.f + __expf(-gs[row][16 + jj]));
        float ov = 1.f / (1.f + __expf(-gs[row][24 + jj]));
        float cold = c[row * H_ + hc];
        float nc = fv * cold + iv * jv;
        float nh = ov * nc;
        c[row * H_ + hc] = nc;
        h_out[row * H_ + hc] = nh;
        out_hid[row * H_ + hc] = nh;
        if (last) {
            cf[row * H_ + hc] = nc;
            hf[row * H_ + hc] = nh;
        }
    }
}

__global__ void init_state(float* h0, float* cc)
{
    int i = blockIdx.x * 256 + threadIdx.x;
    if (i < B_ * H_) { h0[i] = 0.f; cc[i] = 0.f; }
}

// ---------------- launch ------------------------------------------------------------
extern "C" void kernel_launch(void* const* d_in, const int* in_sizes, int n_in,
                              void* d_out, int out_size)
{
    (void)in_sizes; (void)n_in;
    const float* x  = (const float*)d_in[0];
    const float* sb = (const float*)d_in[1];
    const float* mem = (const float*)d_in[3];
    const float* Wq = (const float*)d_in[4];  const float* bq = (const float*)d_in[5];
    const float* Wk = (const float*)d_in[6];  const float* bk = (const float*)d_in[7];
    const float* Wv = (const float*)d_in[8];  const float* bv = (const float*)d_in[9];
    const float* Wo = (const float*)d_in[10]; const float* bo = (const float*)d_in[11];
    const float* W1 = (const float*)d_in[12]; const float* b1 = (const float*)d_in[13];
    const float* W2 = (const float*)d_in[14]; const float* b2 = (const float*)d_in[15];
    const float* Wg = (const float*)d_in[16]; const float* bg = (const float*)d_in[17];
    float* out = (float*)d_out;

    float *q, *k, *v, *ctx, *attn, *ffnh, *ffnx, *gpre, *hbuf, *cbuf;
    cudaGetSymbolAddress((void**)&q,    g_q);
    cudaGetSymbolAddress((void**)&k,    g_k);
    cudaGetSymbolAddress((void**)&v,    g_v);
    cudaGetSymbolAddress((void**)&ctx,  g_ctx);
    cudaGetSymbolAddress((void**)&attn, g_attn);
    cudaGetSymbolAddress((void**)&ffnh, g_ffnh);
    cudaGetSymbolAddress((void**)&ffnx, g_ffnx);
    cudaGetSymbolAddress((void**)&gpre, g_gpre);
    cudaGetSymbolAddress((void**)&hbuf, g_hbuf);
    cudaGetSymbolAddress((void**)&cbuf, g_cbuf);

    dim3 blk(256);

    // projections (tf32 tensor cores)
    mma_gemm<<<dim3(H_ / 128, (T_ * B_) / 128), blk>>>(x,   Wq, bq, q, T_ * B_, H_, H_, H_, 1);
    mma_gemm<<<dim3(H_ / 128, (S_ * B_) / 128), blk>>>(mem, Wk, bk, k, S_ * B_, H_, H_, H_, 1);
    mma_gemm<<<dim3(H_ / 128, (S_ * B_) / 128), blk>>>(mem, Wv, bv, v, S_ * B_, H_, H_, H_, 1);

    // attention
    size_t attn_smem = (size_t)ATT_SMEM_FLOATS * sizeof(float);
    cudaFuncSetAttribute(attn_kernel, cudaFuncAttributeMaxDynamicSharedMemorySize, (int)attn_smem);
    attn_kernel<<<dim3(B_ * NH_, T_ / 64), blk, attn_smem>>>(q, k, v, sb, ctx);

    // output projection
    mma_gemm<<<dim3(H_ / 128, (T_ * B_) / 128), blk>>>(ctx, Wo, bo, attn, T_ * B_, H_, H_, H_, 1);

    // feed-forward
    mma_gemm<<<dim3(F_ / 128, (T_ * B_) / 128), blk>>>(x,    W1, b1, ffnh, T_ * B_, F_, H_, F_, 3);
    mma_gemm<<<dim3(H_ / 128, (T_ * B_) / 128), blk>>>(ffnh, W2, b2, ffnx, T_ * B_, H_, F_, H_, 1);

    // gate precompute: gpre = ffnx @ Wg[0:H] + attn @ Wg[H:2H] + bg
    mma_gemm<<<dim3((4 * H_) / 128, (T_ * B_) / 128), blk>>>(
        ffnx, Wg, bg, gpre, T_ * B_, 4 * H_, H_, 4 * H_, 1);
    mma_gemm<<<dim3((4 * H_) / 128, (T_ * B_) / 128), blk>>>(
        attn, Wg + (size_t)H_ * 4 * H_, nullptr, gpre, T_ * B_, 4 * H_, H_, 4 * H_, 4);

    // recurrence
    init_state<<<(B_ * H_ + 255) / 256, 256>>>(hbuf, cbuf);
    const float* Whh = Wg + (size_t)2 * H_ * 4 * H_;
    int has_tail = out_size >= T_ * B_ * H_ + 2 * B_ * H_;
    float* cf = out + (size_t)T_ * B_ * H_;
    float* hf = cf + B_ * H_;
    for (int t = 0; t < T_; t++) {
        lstm_step_kernel<<<H_ / 8, 256>>>(
            gpre + (size_t)t * B_ * 4 * H_, Whh,
            hbuf + (t & 1) * (B_ * H_), hbuf + ((t + 1) & 1) * (B_ * H_), cbuf,
            out + (size_t)t * B_ * H_, cf, hf,
            (t == T_ - 1 && has_tail) ? 1 : 0);
    }
}

// round 4
// speedup vs baseline: 2.9860x; 1.8632x over previous
#include <cuda_runtime.h>
#include <math.h>
#include <stdint.h>

#define T_ 256
#define S_ 128
#define B_ 32
#define H_ 1024
#define NH_ 16
#define D_ 64
#define F_ 4096

// ---------------- scratch (static device globals; no allocation) ----------------
__device__ float g_q[(size_t)T_ * B_ * H_];
__device__ float g_k[(size_t)S_ * B_ * H_];
__device__ float g_v[(size_t)S_ * B_ * H_];
__device__ float g_ctx[(size_t)T_ * B_ * H_];
__device__ float g_attn[(size_t)T_ * B_ * H_];
__device__ float g_ffnh[(size_t)T_ * B_ * F_];
__device__ float g_ffnx[(size_t)T_ * B_ * H_];
__device__ float g_gpre[(size_t)T_ * B_ * 4 * H_];
__device__ float g_hbuf[2 * B_ * H_];
__device__ float g_cbuf[B_ * H_];
__device__ float g_xr[(size_t)T_ * B_ * H_];
__device__ float g_memr[(size_t)S_ * B_ * H_];
__device__ float g_part[(size_t)32 * 4 * 32 * 128];
__device__ int   g_cnt[32];
// transposed tf32 weights
#define MM_ (1024 * 1024)
__device__ float g_wT[(size_t)24 * MM_];

// ---------------- PTX helpers ----------------------------------------------------
__device__ __forceinline__ uint32_t smem_to_u32(const void* p) {
    uint32_t a;
    asm("{ .reg .u64 t; cvta.to.shared.u64 t, %1; cvt.u32.u64 %0, t; }" : "=r"(a) : "l"(p));
    return a;
}
__device__ __forceinline__ uint32_t f2tf32(float x) {
    uint32_t u;
    asm("cvt.rna.tf32.f32 %0, %1;" : "=r"(u) : "f"(x));
    return u;
}
__device__ __forceinline__ void cp16(uint32_t s, const void* g) {
    asm volatile("cp.async.cg.shared.global [%0], [%1], 16;\n" :: "r"(s), "l"(g));
}
__device__ __forceinline__ void cp_commit() { asm volatile("cp.async.commit_group;\n"); }
template<int N> __device__ __forceinline__ void cp_wait() {
    asm volatile("cp.async.wait_group %0;\n" :: "n"(N));
}
__device__ __forceinline__ void ldsm4(uint32_t& r0, uint32_t& r1, uint32_t& r2,
                                      uint32_t& r3, uint32_t addr) {
    asm volatile("ldmatrix.sync.aligned.m8n8.x4.shared.b16 {%0,%1,%2,%3}, [%4];"
                 : "=r"(r0), "=r"(r1), "=r"(r2), "=r"(r3) : "r"(addr));
}
__device__ __forceinline__ void mma_tf32(float (&d)[4], const uint32_t (&a)[4],
                                         uint32_t b0, uint32_t b1) {
    asm volatile(
        "mma.sync.aligned.m16n8k8.row.col.f32.tf32.tf32.f32 "
        "{%0,%1,%2,%3}, {%4,%5,%6,%7}, {%8,%9}, {%0,%1,%2,%3};\n"
        : "+f"(d[0]), "+f"(d[1]), "+f"(d[2]), "+f"(d[3])
        : "r"(a[0]), "r"(a[1]), "r"(a[2]), "r"(a[3]), "r"(b0), "r"(b1));
}
__device__ __forceinline__ float sigmoidf_(float x) { return 1.f / (1.f + __expf(-x)); }

// ---------------- prepass kernels -------------------------------------------------
__global__ __launch_bounds__(256)
void transpose_tf32(const float* __restrict__ in, float* __restrict__ out, int R, int C)
{
    __shared__ float t[32][33];
    const int bx = blockIdx.x * 32;
    const int by = blockIdx.y * 32;
    const int tx = threadIdx.x & 31;
    const int ty = threadIdx.x >> 5;
#pragma unroll
    for (int i = 0; i < 4; i++)
        t[ty + 8 * i][tx] = in[(size_t)(by + ty + 8 * i) * C + bx + tx];
    __syncthreads();
#pragma unroll
    for (int i = 0; i < 4; i++)
        out[(size_t)(bx + ty + 8 * i) * R + by + tx] =
            __uint_as_float(f2tf32(t[tx][ty + 8 * i]));
}

__global__ __launch_bounds__(256)
void round_tf32(const float* __restrict__ in, float* __restrict__ out, int n)
{
    int i = blockIdx.x * 256 + threadIdx.x;
    for (; i < n; i += gridDim.x * 256)
        out[i] = __uint_as_float(f2tf32(in[i]));
}

__global__ void init_state(float* h, float* cc, int* cnt)
{
    int i = blockIdx.x * 256 + threadIdx.x;
    if (i < 2 * B_ * H_) h[i] = 0.f;
    if (i < B_ * H_) cc[i] = 0.f;
    if (i < 32) cnt[i] = 0;
}

// ---------------- tf32 mma GEMM: C[MxN] = A @ Bt^T ---------------------------------
// A: [M][K] fp32 (already tf32-rounded), dual-source rows [A(kSplit) | A2(K-kSplit)]
// Bt: [N][K] tf32. flags: 1=bias, 2=relu, 8=round output to tf32.
// 128x128x16 tile, 3-stage cp.async, ldmatrix fragments, warp tile 64x32.
#define STG_ 20480   // A 128*80 + B 128*80
__global__ __launch_bounds__(256, 2)
void mm_gemm(const float* __restrict__ A, const float* __restrict__ A2, int kSplit,
             const float* __restrict__ Bt, const float* __restrict__ bias,
             float* __restrict__ C, int M, int N, int K, int flags)
{
    extern __shared__ char smc[];
    const uint32_t sb = smem_to_u32(smc);
    const int tid = threadIdx.x, lane = tid & 31, warp = tid >> 5;
    const int wm = warp >> 2, wn = warp & 3;
    const int m0 = blockIdx.y * 128, n0 = blockIdx.x * 128;
    const int lda2 = K - kSplit;
    const int nkt = K >> 4;

    auto fill = [&](int kt) {
        const int s = kt % 3;
        const uint32_t as = sb + s * STG_;
        const uint32_t bs = as + 10240;
        const int k0 = kt << 4;
#pragma unroll
        for (int i = 0; i < 2; i++) {
            int ch = tid + 256 * i;
            int row = ch >> 2, kh = ch & 3;
            int k = k0 + kh * 4;
            const float* src = (k < kSplit)
                ? A  + (size_t)(m0 + row) * kSplit + k
                : A2 + (size_t)(m0 + row) * lda2 + (k - kSplit);
            cp16(as + row * 80 + kh * 16, src);
        }
#pragma unroll
        for (int i = 0; i < 2; i++) {
            int ch = tid + 256 * i;
            int row = ch >> 2, kh = ch & 3;
            cp16(bs + row * 80 + kh * 16, Bt + (size_t)(n0 + row) * K + k0 + kh * 4);
        }
    };

    float acc[4][4][4];
#pragma unroll
    for (int i = 0; i < 4; i++)
#pragma unroll
        for (int j = 0; j < 4; j++)
#pragma unroll
            for (int r = 0; r < 4; r++) acc[i][j][r] = 0.f;

    fill(0); cp_commit();
    if (nkt > 1) fill(1);
    cp_commit();

    const uint32_t aoff = (uint32_t)((wm * 64 + (lane & 15)) * 80 + (lane >> 4) * 16);
    const uint32_t boff = (uint32_t)((wn * 32 + (lane & 15)) * 80 + (lane >> 4) * 16);

    for (int kt = 0; kt < nkt; kt++) {
        cp_wait<1>();
        __syncthreads();
        if (kt + 2 < nkt) fill(kt + 2);
        cp_commit();
        const uint32_t as = sb + (kt % 3) * STG_;
        const uint32_t bs = as + 10240;
#pragma unroll
        for (int ks = 0; ks < 2; ks++) {
            uint32_t af[4][4], bf[2][4];
#pragma unroll
            for (int mi = 0; mi < 4; mi++)
                ldsm4(af[mi][0], af[mi][1], af[mi][2], af[mi][3],
                      as + aoff + mi * (16 * 80) + ks * 32);
#pragma unroll
            for (int nip = 0; nip < 2; nip++)
                ldsm4(bf[nip][0], bf[nip][1], bf[nip][2], bf[nip][3],
                      bs + boff + nip * (16 * 80) + ks * 32);
#pragma unroll
            for (int mi = 0; mi < 4; mi++)
#pragma unroll
                for (int ni = 0; ni < 4; ni++) {
                    const int nip = ni >> 1, o = ni & 1;
                    mma_tf32(acc[mi][ni], af[mi], bf[nip][o], bf[nip][o + 2]);
                }
        }
    }

    // epilogue: c0=(g,2t) c1=(g,2t+1) c2=(g+8,2t) c3=(g+8,2t+1)
    const int g = lane >> 2, t = lane & 3;
#pragma unroll
    for (int mi = 0; mi < 4; mi++) {
#pragma unroll
        for (int ni = 0; ni < 4; ni++) {
            const int r0 = m0 + wm * 64 + mi * 16 + g;
            const int cc = n0 + wn * 32 + ni * 8 + 2 * t;
            float2 v0 = make_float2(acc[mi][ni][0], acc[mi][ni][1]);
            float2 v1 = make_float2(acc[mi][ni][2], acc[mi][ni][3]);
            if (flags & 1) {
                float2 bb = *(const float2*)(bias + cc);
                v0.x += bb.x; v0.y += bb.y; v1.x += bb.x; v1.y += bb.y;
            }
            if (flags & 2) {
                v0.x = fmaxf(v0.x, 0.f); v0.y = fmaxf(v0.y, 0.f);
                v1.x = fmaxf(v1.x, 0.f); v1.y = fmaxf(v1.y, 0.f);
            }
            if (flags & 8) {
                v0.x = __uint_as_float(f2tf32(v0.x)); v0.y = __uint_as_float(f2tf32(v0.y));
                v1.x = __uint_as_float(f2tf32(v1.x)); v1.y = __uint_as_float(f2tf32(v1.y));
            }
            *(float2*)(C + (size_t)r0 * N + cc) = v0;
            *(float2*)(C + (size_t)(r0 + 8) * N + cc) = v1;
        }
    }
}

// ---------------- attention: per (b,h) block over 64-row t-tile --------------------
#define ATT_PAD 68
#define ATT_SMEM_FLOATS ((64 + 128 + 128) * ATT_PAD + 8 * 128)

__global__ __launch_bounds__(256)
void attn_kernel(const float* __restrict__ q, const float* __restrict__ k,
                 const float* __restrict__ v, const float* __restrict__ sbias,
                 float* __restrict__ ctx)
{
    extern __shared__ float sm[];
    float* Qs = sm;
    float* Ks = sm + 64 * ATT_PAD;
    float* Vs = Ks + 128 * ATT_PAD;
    float* probs = Vs + 128 * ATT_PAD;

    const int b = blockIdx.x / NH_;
    const int h = blockIdx.x % NH_;
    const int t0 = blockIdx.y * 64;
    const int tid = threadIdx.x;
    const int lane = tid & 31;
    const int warp = tid >> 5;
    const int hd = h * D_;

    for (int e = tid; e < 128 * 16; e += 256) {
        int s = e >> 4;
        int d4 = (e & 15) << 2;
        size_t gofs = ((size_t)(s * B_ + b)) * H_ + hd + d4;
        *(float4*)&Ks[s * ATT_PAD + d4] = *(const float4*)&k[gofs];
        *(float4*)&Vs[s * ATT_PAD + d4] = *(const float4*)&v[gofs];
    }
    for (int e = tid; e < 64 * 16; e += 256) {
        int r = e >> 4;
        int d4 = (e & 15) << 2;
        *(float4*)&Qs[r * ATT_PAD + d4] =
            *(const float4*)&q[((size_t)((t0 + r) * B_ + b)) * H_ + hd + d4];
    }
    __syncthreads();

    const float scale = 0.125f;
    float* pw = probs + warp * 128;

    for (int r8 = 0; r8 < 8; r8++) {
        int row = warp * 8 + r8;
        const float4* qrow = (const float4*)&Qs[row * ATT_PAD];
        const float4* k0p = (const float4*)&Ks[(lane) * ATT_PAD];
        const float4* k1p = (const float4*)&Ks[(lane + 32) * ATT_PAD];
        const float4* k2p = (const float4*)&Ks[(lane + 64) * ATT_PAD];
        const float4* k3p = (const float4*)&Ks[(lane + 96) * ATT_PAD];
        float a0 = 0.f, a1 = 0.f, a2 = 0.f, a3 = 0.f;
#pragma unroll
        for (int d4 = 0; d4 < 16; d4++) {
            float4 qv = qrow[d4];
            float4 kv;
            kv = k0p[d4]; a0 += qv.x*kv.x + qv.y*kv.y + qv.z*kv.z + qv.w*kv.w;
            kv = k1p[d4]; a1 += qv.x*kv.x + qv.y*kv.y + qv.z*kv.z + qv.w*kv.w;
            kv = k2p[d4]; a2 += qv.x*kv.x + qv.y*kv.y + qv.z*kv.z + qv.w*kv.w;
            kv = k3p[d4]; a3 += qv.x*kv.x + qv.y*kv.y + qv.z*kv.z + qv.w*kv.w;
        }
        a0 = a0 * scale + sbias[b * S_ + lane];
        a1 = a1 * scale + sbias[b * S_ + lane + 32];
        a2 = a2 * scale + sbias[b * S_ + lane + 64];
        a3 = a3 * scale + sbias[b * S_ + lane + 96];

        float mx = fmaxf(fmaxf(a0, a1), fmaxf(a2, a3));
#pragma unroll
        for (int off = 16; off; off >>= 1)
            mx = fmaxf(mx, __shfl_xor_sync(0xffffffffu, mx, off));
        float e0 = __expf(a0 - mx), e1 = __expf(a1 - mx);
        float e2 = __expf(a2 - mx), e3 = __expf(a3 - mx);
        float ssum = e0 + e1 + e2 + e3;
#pragma unroll
        for (int off = 16; off; off >>= 1)
            ssum += __shfl_xor_sync(0xffffffffu, ssum, off);
        float inv = 1.f / ssum;

        pw[lane] = e0 * inv; pw[lane + 32] = e1 * inv;
        pw[lane + 64] = e2 * inv; pw[lane + 96] = e3 * inv;
        __syncwarp();

        float c0 = 0.f, c1 = 0.f;
#pragma unroll 4
        for (int s = 0; s < 128; s++) {
            float p = pw[s];
            c0 += p * Vs[s * ATT_PAD + lane];
            c1 += p * Vs[s * ATT_PAD + lane + 32];
        }
        // round ctx to tf32 (feeds Wo GEMM)
        float* crow = &ctx[((size_t)((t0 + row) * B_ + b)) * H_ + hd];
        crow[lane] = __uint_as_float(f2tf32(c0));
        crow[lane + 32] = __uint_as_float(f2tf32(c1));
        __syncwarp();
    }
}

// ---------------- LSTM recurrent step: tensor-core split-K + last-CTA fuse ---------
// grid (32 nblk, 4 ksplit), 256 thr. CTA computes g-partial[32 x 128] for hidden
// cols [nblk*32, +32) across 4 gates, K-slice 256. Last-arriving CTA per nblk sums
// the 4 partials in fixed order, adds gpre, applies gates, updates state.
#define LSTG 23040   // A 32*144 + B 128*144
__global__ __launch_bounds__(256)
void lstm_tc(const float* __restrict__ gpre_t, const float* __restrict__ WhhT,
             const float* __restrict__ hin, float* __restrict__ hout,
             float* __restrict__ c, float* __restrict__ out_h,
             float* __restrict__ cf, float* __restrict__ hf,
             float* __restrict__ part, int* __restrict__ cnt, int lastStep)
{
    extern __shared__ char smc[];
    const uint32_t sb = smem_to_u32(smc);
    __shared__ int is_last;
    const int tid = threadIdx.x, lane = tid & 31, warp = tid >> 5;
    const int nblk = blockIdx.x, ksp = blockIdx.y;
    const int c0 = nblk * 32, k0 = ksp * 256;

    auto fill = [&](int kt) {
        const int s = kt % 3;
        const uint32_t as = sb + s * LSTG;
        const uint32_t bs = as + 4608;
        const int kb = k0 + kt * 32;
        {
            int row = tid >> 3, kh = tid & 7;
            cp16(as + row * 144 + kh * 16, hin + row * H_ + kb + kh * 4);
        }
#pragma unroll
        for (int i = 0; i < 4; i++) {
            int id = tid + 256 * i;
            int ln = id >> 3, kh = id & 7;
            int grow = (ln >> 5) * H_ + c0 + (ln & 31);
            cp16(bs + ln * 144 + kh * 16, WhhT + (size_t)grow * H_ + kb + kh * 4);
        }
    };

    float acc[2][2][4];
#pragma unroll
    for (int i = 0; i < 2; i++)
#pragma unroll
        for (int j = 0; j < 2; j++)
#pragma unroll
            for (int r = 0; r < 4; r++) acc[i][j][r] = 0.f;

    fill(0); cp_commit();
    fill(1); cp_commit();

    const uint32_t aoff = (uint32_t)((lane & 15) * 144 + (lane >> 4) * 16);
    const uint32_t boff = (uint32_t)((warp * 16 + (lane & 15)) * 144 + (lane >> 4) * 16);

    for (int kt = 0; kt < 8; kt++) {
        cp_wait<1>();
        __syncthreads();
        if (kt + 2 < 8) fill(kt + 2);
        cp_commit();
        const uint32_t as = sb + (kt % 3) * LSTG;
        const uint32_t bs = as + 4608;
#pragma unroll
        for (int ks = 0; ks < 4; ks++) {
            uint32_t af[2][4], bf[4];
#pragma unroll
            for (int mi = 0; mi < 2; mi++)
                ldsm4(af[mi][0], af[mi][1], af[mi][2], af[mi][3],
                      as + aoff + mi * (16 * 144) + ks * 32);
            ldsm4(bf[0], bf[1], bf[2], bf[3], bs + boff + ks * 32);
#pragma unroll
            for (int mi = 0; mi < 2; mi++) {
                mma_tf32(acc[mi][0], af[mi], bf[0], bf[2]);
                mma_tf32(acc[mi][1], af[mi], bf[1], bf[3]);
            }
        }
    }

    // write partial [32 rows][128 ln]
    float* ps = part + ((size_t)(nblk * 4 + ksp)) * (32 * 128);
    const int g = lane >> 2, t = lane & 3;
#pragma unroll
    for (int mi = 0; mi < 2; mi++)
#pragma unroll
        for (int ni = 0; ni < 2; ni++) {
            const int row = mi * 16 + g;
            const int col = warp * 16 + ni * 8 + 2 * t;
            *(float2*)&ps[row * 128 + col] = make_float2(acc[mi][ni][0], acc[mi][ni][1]);
            *(float2*)&ps[(row + 8) * 128 + col] = make_float2(acc[mi][ni][2], acc[mi][ni][3]);
        }
    __threadfence();
    __syncthreads();
    if (tid == 0) {
        int prev = atomicAdd(&cnt[nblk], 1);
        is_last = (prev == 3);
        if (prev == 3) cnt[nblk] = 0;   // reset for next step (stream-serialized)
    }
    __syncthreads();
    if (!is_last) return;
    __threadfence();

    // fused reduce + gates: thread -> (row = tid>>3, 4 cols at (tid&7)*4)
    const int row = tid >> 3;
    const int j4 = (tid & 7) * 4;
    const float* pb = part + (size_t)nblk * 4 * (32 * 128);
    float gv[4][4];
#pragma unroll
    for (int gi = 0; gi < 4; gi++) {
        float4 s = *(const float4*)&gpre_t[(size_t)row * (4 * H_) + gi * H_ + c0 + j4];
#pragma unroll
        for (int sp = 0; sp < 4; sp++) {
            float4 p = *(const float4*)&pb[sp * (32 * 128) + row * 128 + gi * 32 + j4];
            s.x += p.x; s.y += p.y; s.z += p.z; s.w += p.w;
        }
        gv[gi][0] = s.x; gv[gi][1] = s.y; gv[gi][2] = s.z; gv[gi][3] = s.w;
    }
#pragma unroll
    for (int l = 0; l < 4; l++) {
        const int idx = row * H_ + c0 + j4 + l;
        float iv = sigmoidf_(gv[0][l]);
        float jv = tanhf(gv[1][l]);
        float fv = sigmoidf_(gv[2][l]);
        float ov = sigmoidf_(gv[3][l]);
        float cold = c[idx];
        float nc = fv * cold + iv * jv;
        float nh = ov * nc;               // THUMT LSTMCell: activation=None
        c[idx] = nc;
        out_h[idx] = nh;
        hout[idx] = __uint_as_float(f2tf32(nh));   // rounded for next-step MMA
        if (lastStep) { cf[idx] = nc; hf[idx] = nh; }
    }
}

// ---------------- launch ------------------------------------------------------------
extern "C" void kernel_launch(void* const* d_in, const int* in_sizes, int n_in,
                              void* d_out, int out_size)
{
    (void)in_sizes; (void)n_in;
    const float* x  = (const float*)d_in[0];
    const float* sb = (const float*)d_in[1];
    const float* mem = (const float*)d_in[3];
    const float* bq = (const float*)d_in[5];
    const float* bk = (const float*)d_in[7];
    const float* bv = (const float*)d_in[9];
    const float* bo = (const float*)d_in[11];
    const float* b1 = (const float*)d_in[13];
    const float* b2 = (const float*)d_in[15];
    const float* Wg = (const float*)d_in[16];
    const float* bg = (const float*)d_in[17];
    const float* Wq = (const float*)d_in[4];
    const float* Wk = (const float*)d_in[6];
    const float* Wv = (const float*)d_in[8];
    const float* Wo = (const float*)d_in[10];
    const float* W1 = (const float*)d_in[12];
    const float* W2 = (const float*)d_in[14];
    float* out = (float*)d_out;

    float *q, *k, *v, *ctx, *attn, *ffnh, *ffnx, *gpre, *hbuf, *cbuf, *wT, *xr, *memr, *part;
    int* cnt;
    cudaGetSymbolAddress((void**)&q,    g_q);
    cudaGetSymbolAddress((void**)&k,    g_k);
    cudaGetSymbolAddress((void**)&v,    g_v);
    cudaGetSymbolAddress((void**)&ctx,  g_ctx);
    cudaGetSymbolAddress((void**)&attn, g_attn);
    cudaGetSymbolAddress((void**)&ffnh, g_ffnh);
    cudaGetSymbolAddress((void**)&ffnx, g_ffnx);
    cudaGetSymbolAddress((void**)&gpre, g_gpre);
    cudaGetSymbolAddress((void**)&hbuf, g_hbuf);
    cudaGetSymbolAddress((void**)&cbuf, g_cbuf);
    cudaGetSymbolAddress((void**)&wT,   g_wT);
    cudaGetSymbolAddress((void**)&xr,   g_xr);
    cudaGetSymbolAddress((void**)&memr, g_memr);
    cudaGetSymbolAddress((void**)&part, g_part);
    cudaGetSymbolAddress((void**)&cnt,  g_cnt);

    float* WqT = wT;
    float* WkT = wT + (size_t)1 * MM_;
    float* WvT = wT + (size_t)2 * MM_;
    float* WoT = wT + (size_t)3 * MM_;
    float* W1T = wT + (size_t)4 * MM_;
    float* W2T = wT + (size_t)8 * MM_;
    float* WgT = wT + (size_t)12 * MM_;
    float* WhhT = wT + (size_t)20 * MM_;

    dim3 blk(256);

    // prepass: weight transpose + tf32 round; activation rounding
    transpose_tf32<<<dim3(H_ / 32, H_ / 32), blk>>>(Wq, WqT, H_, H_);
    transpose_tf32<<<dim3(H_ / 32, H_ / 32), blk>>>(Wk, WkT, H_, H_);
    transpose_tf32<<<dim3(H_ / 32, H_ / 32), blk>>>(Wv, WvT, H_, H_);
    transpose_tf32<<<dim3(H_ / 32, H_ / 32), blk>>>(Wo, WoT, H_, H_);
    transpose_tf32<<<dim3(F_ / 32, H_ / 32), blk>>>(W1, W1T, H_, F_);
    transpose_tf32<<<dim3(H_ / 32, F_ / 32), blk>>>(W2, W2T, F_, H_);
    transpose_tf32<<<dim3(F_ / 32, (2 * H_) / 32), blk>>>(Wg, WgT, 2 * H_, F_);
    transpose_tf32<<<dim3(F_ / 32, H_ / 32), blk>>>(
        Wg + (size_t)2 * H_ * 4 * H_, WhhT, H_, F_);
    round_tf32<<<1024, blk>>>(x, xr, T_ * B_ * H_);
    round_tf32<<<1024, blk>>>(mem, memr, S_ * B_ * H_);

    const int GSM = 3 * STG_;   // 61440
    cudaFuncSetAttribute(mm_gemm, cudaFuncAttributeMaxDynamicSharedMemorySize, GSM);
    const int LSM = 3 * LSTG;   // 69120
    cudaFuncSetAttribute(lstm_tc, cudaFuncAttributeMaxDynamicSharedMemorySize, LSM);

    // projections
    mm_gemm<<<dim3(H_ / 128, (T_ * B_) / 128), blk, GSM>>>(
        xr, xr, H_, WqT, bq, q, T_ * B_, H_, H_, 1);
    mm_gemm<<<dim3(H_ / 128, (S_ * B_) / 128), blk, GSM>>>(
        memr, memr, H_, WkT, bk, k, S_ * B_, H_, H_, 1);
    mm_gemm<<<dim3(H_ / 128, (S_ * B_) / 128), blk, GSM>>>(
        memr, memr, H_, WvT, bv, v, S_ * B_, H_, H_, 1);

    // attention (fp32, rounds ctx on store)
    size_t attn_smem = (size_t)ATT_SMEM_FLOATS * sizeof(float);
    cudaFuncSetAttribute(attn_kernel, cudaFuncAttributeMaxDynamicSharedMemorySize,
                         (int)attn_smem);
    attn_kernel<<<dim3(B_ * NH_, T_ / 64), blk, attn_smem>>>(q, k, v, sb, ctx);

    // output projection (rounded output feeds gpre GEMM)
    mm_gemm<<<dim3(H_ / 128, (T_ * B_) / 128), blk, GSM>>>(
        ctx, ctx, H_, WoT, bo, attn, T_ * B_, H_, H_, 1 | 8);

    // feed-forward (ffnh rounded+relu, ffnx rounded)
    mm_gemm<<<dim3(F_ / 128, (T_ * B_) / 128), blk, GSM>>>(
        xr, xr, H_, W1T, b1, ffnh, T_ * B_, F_, H_, 1 | 2 | 8);
    mm_gemm<<<dim3(H_ / 128, (T_ * B_) / 128), blk, GSM>>>(
        ffnh, ffnh, F_, W2T, b2, ffnx, T_ * B_, H_, F_, 1 | 8);

    // gate precompute (fused dual-source K=2048): gpre = [ffnx|attn] @ WgT^T + bg
    mm_gemm<<<dim3((4 * H_) / 128, (T_ * B_) / 128), blk, GSM>>>(
        ffnx, attn, H_, WgT, bg, gpre, T_ * B_, 4 * H_, 2 * H_, 1);

    // recurrence
    init_state<<<(2 * B_ * H_ + 255) / 256, 256>>>(hbuf, cbuf, cnt);
    int has_tail = out_size >= T_ * B_ * H_ + 2 * B_ * H_;
    float* cf = out + (size_t)T_ * B_ * H_;
    float* hf = cf + B_ * H_;
    for (int t = 0; t < T_; t++) {
        lstm_tc<<<dim3(32, 4), blk, LSM>>>(
            gpre + (size_t)t * B_ * 4 * H_, WhhT,
            hbuf + (t & 1) * (B_ * H_), hbuf + ((t + 1) & 1) * (B_ * H_),
            cbuf, out + (size_t)t * B_ * H_, cf, hf, part, cnt,
            (t == T_ - 1 && has_tail) ? 1 : 0);
    }
}

// round 5
// speedup vs baseline: 3.2151x; 1.0767x over previous
#include <cuda_runtime.h>
#include <math.h>
#include <stdint.h>

#define T_ 256
#define S_ 128
#define B_ 32
#define H_ 1024
#define NH_ 16
#define D_ 64
#define F_ 4096

// ---------------- scratch (static device globals; no allocation) ----------------
__device__ float g_q[(size_t)T_ * B_ * H_];
__device__ float g_k[(size_t)S_ * B_ * H_];
__device__ float g_v[(size_t)S_ * B_ * H_];
__device__ float g_ctx[(size_t)T_ * B_ * H_];
__device__ float g_attn[(size_t)T_ * B_ * H_];
__device__ float g_ffnh[(size_t)T_ * B_ * F_];
__device__ float g_ffnx[(size_t)T_ * B_ * H_];
__device__ float g_gpre[(size_t)T_ * B_ * 4 * H_];
__device__ float g_hbuf[2 * B_ * H_];
__device__ float g_cbuf[B_ * H_];
__device__ float g_xr[(size_t)T_ * B_ * H_];
__device__ float g_memr[(size_t)S_ * B_ * H_];
__device__ int   g_ctr[T_];
// transposed tf32 weights
#define MM_ (1024 * 1024)
__device__ float g_wT[(size_t)24 * MM_];

// ---------------- PTX helpers ----------------------------------------------------
__device__ __forceinline__ uint32_t smem_to_u32(const void* p) {
    uint32_t a;
    asm("{ .reg .u64 t; cvta.to.shared.u64 t, %1; cvt.u32.u64 %0, t; }" : "=r"(a) : "l"(p));
    return a;
}
__device__ __forceinline__ uint32_t f2tf32(float x) {
    uint32_t u;
    asm("cvt.rna.tf32.f32 %0, %1;" : "=r"(u) : "f"(x));
    return u;
}
__device__ __forceinline__ void cp16(uint32_t s, const void* g) {
    asm volatile("cp.async.cg.shared.global [%0], [%1], 16;\n" :: "r"(s), "l"(g));
}
__device__ __forceinline__ void cp_commit() { asm volatile("cp.async.commit_group;\n"); }
template<int N> __device__ __forceinline__ void cp_wait() {
    asm volatile("cp.async.wait_group %0;\n" :: "n"(N));
}
__device__ __forceinline__ void ldsm4(uint32_t& r0, uint32_t& r1, uint32_t& r2,
                                      uint32_t& r3, uint32_t addr) {
    asm volatile("ldmatrix.sync.aligned.m8n8.x4.shared.b16 {%0,%1,%2,%3}, [%4];"
                 : "=r"(r0), "=r"(r1), "=r"(r2), "=r"(r3) : "r"(addr));
}
__device__ __forceinline__ void mma_tf32(float (&d)[4], const uint32_t (&a)[4],
                                         uint32_t b0, uint32_t b1) {
    asm volatile(
        "mma.sync.aligned.m16n8k8.row.col.f32.tf32.tf32.f32 "
        "{%0,%1,%2,%3}, {%4,%5,%6,%7}, {%8,%9}, {%0,%1,%2,%3};\n"
        : "+f"(d[0]), "+f"(d[1]), "+f"(d[2]), "+f"(d[3])
        : "r"(a[0]), "r"(a[1]), "r"(a[2]), "r"(a[3]), "r"(b0), "r"(b1));
}
__device__ __forceinline__ float sigmoidf_(float x) { return 1.f / (1.f + __expf(-x)); }

// ---------------- prepass kernels -------------------------------------------------
__global__ __launch_bounds__(256)
void transpose_tf32(const float* __restrict__ in, float* __restrict__ out, int R, int C)
{
    __shared__ float t[32][33];
    const int bx = blockIdx.x * 32;
    const int by = blockIdx.y * 32;
    const int tx = threadIdx.x & 31;
    const int ty = threadIdx.x >> 5;
#pragma unroll
    for (int i = 0; i < 4; i++)
        t[ty + 8 * i][tx] = in[(size_t)(by + ty + 8 * i) * C + bx + tx];
    __syncthreads();
#pragma unroll
    for (int i = 0; i < 4; i++)
        out[(size_t)(bx + ty + 8 * i) * R + by + tx] =
            __uint_as_float(f2tf32(t[tx][ty + 8 * i]));
}

__global__ __launch_bounds__(256)
void round_tf32(const float* __restrict__ in, float* __restrict__ out, int n)
{
    int i = blockIdx.x * 256 + threadIdx.x;
    for (; i < n; i += gridDim.x * 256)
        out[i] = __uint_as_float(f2tf32(in[i]));
}

__global__ void init_state(float* h, float* cc, int* ctr)
{
    int i = blockIdx.x * 256 + threadIdx.x;
    if (i < 2 * B_ * H_) h[i] = 0.f;
    if (i < B_ * H_) cc[i] = 0.f;
    if (i < T_) ctr[i] = 0;
}

// ---------------- tf32 mma GEMM: C[MxN] = A @ Bt^T ---------------------------------
// A: [M][K] fp32 (already tf32-rounded), dual-source rows [A(kSplit) | A2(K-kSplit)]
// Bt: [N][K] tf32. flags: 1=bias, 2=relu, 8=round output to tf32.
#define STG_ 20480   // A 128*80 + B 128*80
__global__ __launch_bounds__(256, 2)
void mm_gemm(const float* __restrict__ A, const float* __restrict__ A2, int kSplit,
             const float* __restrict__ Bt, const float* __restrict__ bias,
             float* __restrict__ C, int M, int N, int K, int flags)
{
    extern __shared__ char smc[];
    const uint32_t sb = smem_to_u32(smc);
    const int tid = threadIdx.x, lane = tid & 31, warp = tid >> 5;
    const int wm = warp >> 2, wn = warp & 3;
    const int m0 = blockIdx.y * 128, n0 = blockIdx.x * 128;
    const int lda2 = K - kSplit;
    const int nkt = K >> 4;

    auto fill = [&](int kt) {
        const int s = kt % 3;
        const uint32_t as = sb + s * STG_;
        const uint32_t bs = as + 10240;
        const int k0 = kt << 4;
#pragma unroll
        for (int i = 0; i < 2; i++) {
            int ch = tid + 256 * i;
            int row = ch >> 2, kh = ch & 3;
            int k = k0 + kh * 4;
            const float* src = (k < kSplit)
                ? A  + (size_t)(m0 + row) * kSplit + k
                : A2 + (size_t)(m0 + row) * lda2 + (k - kSplit);
            cp16(as + row * 80 + kh * 16, src);
        }
#pragma unroll
        for (int i = 0; i < 2; i++) {
            int ch = tid + 256 * i;
            int row = ch >> 2, kh = ch & 3;
            cp16(bs + row * 80 + kh * 16, Bt + (size_t)(n0 + row) * K + k0 + kh * 4);
        }
    };

    float acc[4][4][4];
#pragma unroll
    for (int i = 0; i < 4; i++)
#pragma unroll
        for (int j = 0; j < 4; j++)
#pragma unroll
            for (int r = 0; r < 4; r++) acc[i][j][r] = 0.f;

    fill(0); cp_commit();
    if (nkt > 1) fill(1);
    cp_commit();

    const uint32_t aoff = (uint32_t)((wm * 64 + (lane & 15)) * 80 + (lane >> 4) * 16);
    const uint32_t boff = (uint32_t)((wn * 32 + (lane & 15)) * 80 + (lane >> 4) * 16);

    for (int kt = 0; kt < nkt; kt++) {
        cp_wait<1>();
        __syncthreads();
        if (kt + 2 < nkt) fill(kt + 2);
        cp_commit();
        const uint32_t as = sb + (kt % 3) * STG_;
        const uint32_t bs = as + 10240;
#pragma unroll
        for (int ks = 0; ks < 2; ks++) {
            uint32_t af[4][4], bf[2][4];
#pragma unroll
            for (int mi = 0; mi < 4; mi++)
                ldsm4(af[mi][0], af[mi][1], af[mi][2], af[mi][3],
                      as + aoff + mi * (16 * 80) + ks * 32);
#pragma unroll
            for (int nip = 0; nip < 2; nip++)
                ldsm4(bf[nip][0], bf[nip][1], bf[nip][2], bf[nip][3],
                      bs + boff + nip * (16 * 80) + ks * 32);
#pragma unroll
            for (int mi = 0; mi < 4; mi++)
#pragma unroll
                for (int ni = 0; ni < 4; ni++) {
                    const int nip = ni >> 1, o = ni & 1;
                    mma_tf32(acc[mi][ni], af[mi], bf[nip][o], bf[nip][o + 2]);
                }
        }
    }

    const int g = lane >> 2, t = lane & 3;
#pragma unroll
    for (int mi = 0; mi < 4; mi++) {
#pragma unroll
        for (int ni = 0; ni < 4; ni++) {
            const int r0 = m0 + wm * 64 + mi * 16 + g;
            const int cc = n0 + wn * 32 + ni * 8 + 2 * t;
            float2 v0 = make_float2(acc[mi][ni][0], acc[mi][ni][1]);
            float2 v1 = make_float2(acc[mi][ni][2], acc[mi][ni][3]);
            if (flags & 1) {
                float2 bb = *(const float2*)(bias + cc);
                v0.x += bb.x; v0.y += bb.y; v1.x += bb.x; v1.y += bb.y;
            }
            if (flags & 2) {
                v0.x = fmaxf(v0.x, 0.f); v0.y = fmaxf(v0.y, 0.f);
                v1.x = fmaxf(v1.x, 0.f); v1.y = fmaxf(v1.y, 0.f);
            }
            if (flags & 8) {
                v0.x = __uint_as_float(f2tf32(v0.x)); v0.y = __uint_as_float(f2tf32(v0.y));
                v1.x = __uint_as_float(f2tf32(v1.x)); v1.y = __uint_as_float(f2tf32(v1.y));
            }
            *(float2*)(C + (size_t)r0 * N + cc) = v0;
            *(float2*)(C + (size_t)(r0 + 8) * N + cc) = v1;
        }
    }
}

// ---------------- attention ---------------------------------------------------------
#define ATT_PAD 68
#define ATT_SMEM_FLOATS ((64 + 128 + 128) * ATT_PAD + 8 * 128)

__global__ __launch_bounds__(256)
void attn_kernel(const float* __restrict__ q, const float* __restrict__ k,
                 const float* __restrict__ v, const float* __restrict__ sbias,
                 float* __restrict__ ctx)
{
    extern __shared__ float sm[];
    float* Qs = sm;
    float* Ks = sm + 64 * ATT_PAD;
    float* Vs = Ks + 128 * ATT_PAD;
    float* probs = Vs + 128 * ATT_PAD;

    const int b = blockIdx.x / NH_;
    const int h = blockIdx.x % NH_;
    const int t0 = blockIdx.y * 64;
    const int tid = threadIdx.x;
    const int lane = tid & 31;
    const int warp = tid >> 5;
    const int hd = h * D_;

    for (int e = tid; e < 128 * 16; e += 256) {
        int s = e >> 4;
        int d4 = (e & 15) << 2;
        size_t gofs = ((size_t)(s * B_ + b)) * H_ + hd + d4;
        *(float4*)&Ks[s * ATT_PAD + d4] = *(const float4*)&k[gofs];
        *(float4*)&Vs[s * ATT_PAD + d4] = *(const float4*)&v[gofs];
    }
    for (int e = tid; e < 64 * 16; e += 256) {
        int r = e >> 4;
        int d4 = (e & 15) << 2;
        *(float4*)&Qs[r * ATT_PAD + d4] =
            *(const float4*)&q[((size_t)((t0 + r) * B_ + b)) * H_ + hd + d4];
    }
    __syncthreads();

    const float scale = 0.125f;
    float* pw = probs + warp * 128;

    for (int r8 = 0; r8 < 8; r8++) {
        int row = warp * 8 + r8;
        const float4* qrow = (const float4*)&Qs[row * ATT_PAD];
        const float4* k0p = (const float4*)&Ks[(lane) * ATT_PAD];
        const float4* k1p = (const float4*)&Ks[(lane + 32) * ATT_PAD];
        const float4* k2p = (const float4*)&Ks[(lane + 64) * ATT_PAD];
        const float4* k3p = (const float4*)&Ks[(lane + 96) * ATT_PAD];
        float a0 = 0.f, a1 = 0.f, a2 = 0.f, a3 = 0.f;
#pragma unroll
        for (int d4 = 0; d4 < 16; d4++) {
            float4 qv = qrow[d4];
            float4 kv;
            kv = k0p[d4]; a0 += qv.x*kv.x + qv.y*kv.y + qv.z*kv.z + qv.w*kv.w;
            kv = k1p[d4]; a1 += qv.x*kv.x + qv.y*kv.y + qv.z*kv.z + qv.w*kv.w;
            kv = k2p[d4]; a2 += qv.x*kv.x + qv.y*kv.y + qv.z*kv.z + qv.w*kv.w;
            kv = k3p[d4]; a3 += qv.x*kv.x + qv.y*kv.y + qv.z*kv.z + qv.w*kv.w;
        }
        a0 = a0 * scale + sbias[b * S_ + lane];
        a1 = a1 * scale + sbias[b * S_ + lane + 32];
        a2 = a2 * scale + sbias[b * S_ + lane + 64];
        a3 = a3 * scale + sbias[b * S_ + lane + 96];

        float mx = fmaxf(fmaxf(a0, a1), fmaxf(a2, a3));
#pragma unroll
        for (int off = 16; off; off >>= 1)
            mx = fmaxf(mx, __shfl_xor_sync(0xffffffffu, mx, off));
        float e0 = __expf(a0 - mx), e1 = __expf(a1 - mx);
        float e2 = __expf(a2 - mx), e3 = __expf(a3 - mx);
        float ssum = e0 + e1 + e2 + e3;
#pragma unroll
        for (int off = 16; off; off >>= 1)
            ssum += __shfl_xor_sync(0xffffffffu, ssum, off);
        float inv = 1.f / ssum;

        pw[lane] = e0 * inv; pw[lane + 32] = e1 * inv;
        pw[lane + 64] = e2 * inv; pw[lane + 96] = e3 * inv;
        __syncwarp();

        float c0 = 0.f, c1 = 0.f;
#pragma unroll 4
        for (int s = 0; s < 128; s++) {
            float p = pw[s];
            c0 += p * Vs[s * ATT_PAD + lane];
            c1 += p * Vs[s * ATT_PAD + lane + 32];
        }
        float* crow = &ctx[((size_t)((t0 + row) * B_ + b)) * H_ + hd];
        crow[lane] = __uint_as_float(f2tf32(c0));
        crow[lane + 32] = __uint_as_float(f2tf32(c1));
        __syncwarp();
    }
}

// ---------------- persistent LSTM recurrence ---------------------------------------
// 128 CTAs, 1/SM. CTA n owns hidden cols [n*8, n*8+8) => 32 g-cols (4 gates x 8).
// Whh slice (32 g-cols x 1024 K, tf32) lives in smem for all 256 steps.
// Per step: stream h[32x1024] via 3-stage cp.async; 8 warps = 2m x 2n x 2k tiles of
// m16n16 MMA; smem-reduce k-halves; fused gates; grid barrier (per-step counter).
#define LP_BPITCH 4112
#define LP_APITCH 144
#define LP_ASTG   (32 * LP_APITCH)                 // 4608
#define LP_AOFF   131584                            // 32 * LP_BPITCH
#define LP_POFF   (LP_AOFF + 3 * LP_ASTG)           // 145408
#define LP_SMEM   (LP_POFF + 8 * 256 * 4)           // 153600

__global__ __launch_bounds__(256, 1)
void lstm_persist(const float* __restrict__ gpre, const float* __restrict__ WhhT,
                  float* __restrict__ hbuf, float* __restrict__ cbuf,
                  float* __restrict__ out, float* __restrict__ cf,
                  float* __restrict__ hf, int* __restrict__ ctr, int has_tail)
{
    extern __shared__ char smc[];
    const uint32_t sb = smem_to_u32(smc);
    const uint32_t Bs = sb;
    const uint32_t As = sb + LP_AOFF;
    float* part = (float*)(smc + LP_POFF);
    const int tid = threadIdx.x, lane = tid & 31, warp = tid >> 5;
    const int c0 = blockIdx.x * 8;

    // one-time: Whh slice -> smem. g-row (gate*8+j) maps WhhT row gate*1024+c0+j.
#pragma unroll 4
    for (int i = 0; i < 32; i++) {
        int id = tid + 256 * i;
        int row = id >> 8, ch = id & 255;
        int gate = row >> 3, j = row & 7;
        cp16(Bs + row * LP_BPITCH + ch * 16,
             WhhT + (size_t)(gate * H_ + c0 + j) * H_ + ch * 4);
    }
    cp_commit(); cp_wait<0>(); __syncthreads();

    const int wm = warp & 1, wn = (warp >> 1) & 1, wk = warp >> 2;
    const uint32_t aoff = (uint32_t)((wm * 16 + (lane & 15)) * LP_APITCH + (lane >> 4) * 16);
    const uint32_t boff = (uint32_t)((wn * 16 + (lane & 15)) * LP_BPITCH + (lane >> 4) * 16);
    const int row_e = tid >> 3, j_e = tid & 7;   // epilogue: batch row, hidden col

    for (int t = 0; t < T_; t++) {
        const float* hin = hbuf + (t & 1) * (B_ * H_);
        float* hout = hbuf + (1 - (t & 1)) * (B_ * H_);
        const float* gp = gpre + (size_t)t * B_ * 4 * H_;

        float gpv[4];
#pragma unroll
        for (int gi = 0; gi < 4; gi++)
            gpv[gi] = __ldg(gp + (size_t)row_e * (4 * H_) + gi * H_ + c0 + j_e);

        // A stream: tile kt = h[:, kt*32 .. +32)
        {
            int row = tid >> 3, kh = tid & 7;
            cp16(As + 0 * LP_ASTG + row * LP_APITCH + kh * 16, hin + row * H_ + 0 * 32 + kh * 4);
            cp_commit();
            cp16(As + 1 * LP_ASTG + row * LP_APITCH + kh * 16, hin + row * H_ + 1 * 32 + kh * 4);
            cp_commit();
        }

        float acc[2][4];
#pragma unroll
        for (int i = 0; i < 2; i++)
#pragma unroll
            for (int r = 0; r < 4; r++) acc[i][r] = 0.f;

        for (int kt = 0; kt < 32; kt++) {
            cp_wait<1>();
            __syncthreads();
            if (kt + 2 < 32) {
                int row = tid >> 3, kh = tid & 7;
                cp16(As + ((kt + 2) % 3) * LP_ASTG + row * LP_APITCH + kh * 16,
                     hin + row * H_ + (kt + 2) * 32 + kh * 4);
            }
            cp_commit();
            if ((kt >> 4) == wk) {
                const uint32_t as_ = As + (kt % 3) * LP_ASTG;
#pragma unroll
                for (int s = 0; s < 4; s++) {
                    uint32_t af[4], b0, b1, b2, b3;
                    ldsm4(af[0], af[1], af[2], af[3], as_ + aoff + s * 32);
                    ldsm4(b0, b1, b2, b3, Bs + boff + (uint32_t)kt * 128 + s * 32);
                    mma_tf32(acc[0], af, b0, b2);
                    mma_tf32(acc[1], af, b1, b3);
                }
            }
        }

        // store per-warp partials [16x16]
        {
            const int g = lane >> 2, tq = lane & 3;
            float* pw = part + warp * 256;
#pragma unroll
            for (int ni = 0; ni < 2; ni++) {
                *(float2*)&pw[g * 16 + ni * 8 + 2 * tq] = make_float2(acc[ni][0], acc[ni][1]);
                *(float2*)&pw[(g + 8) * 16 + ni * 8 + 2 * tq] = make_float2(acc[ni][2], acc[ni][3]);
            }
        }
        __syncthreads();

        // combine k-halves + gpre; gates; state update
        {
            float gv[4];
#pragma unroll
            for (int gate = 0; gate < 4; gate++) {
                int ncol = gate * 8 + j_e;
                int w0 = (row_e >> 4) | ((ncol >> 4) << 1);
                int idx = (row_e & 15) * 16 + (ncol & 15);
                gv[gate] = part[w0 * 256 + idx] + part[(w0 + 4) * 256 + idx] + gpv[gate];
            }
            const int idx_h = row_e * H_ + c0 + j_e;
            float iv = sigmoidf_(gv[0]);
            float jv = tanhf(gv[1]);
            float fv = sigmoidf_(gv[2]);
            float ov = sigmoidf_(gv[3]);
            float nc = fv * cbuf[idx_h] + iv * jv;
            float nh = ov * nc;                       // THUMT LSTMCell: activation=None
            cbuf[idx_h] = nc;
            out[(size_t)t * B_ * H_ + idx_h] = nh;
            hout[idx_h] = __uint_as_float(f2tf32(nh));
            if (has_tail && t == T_ - 1) { cf[idx_h] = nc; hf[idx_h] = nh; }
        }

        // grid barrier
        __threadfence();
        __syncthreads();
        if (tid == 0) {
            atomicAdd(&ctr[t], 1);
            while (atomicAdd(&ctr[t], 0) < 128) __nanosleep(64);
        }
        __syncthreads();
        __threadfence();
    }
}

// ---------------- launch ------------------------------------------------------------
extern "C" void kernel_launch(void* const* d_in, const int* in_sizes, int n_in,
                              void* d_out, int out_size)
{
    (void)in_sizes; (void)n_in;
    const float* x  = (const float*)d_in[0];
    const float* sb = (const float*)d_in[1];
    const float* mem = (const float*)d_in[3];
    const float* Wq = (const float*)d_in[4];  const float* bq = (const float*)d_in[5];
    const float* Wk = (const float*)d_in[6];  const float* bk = (const float*)d_in[7];
    const float* Wv = (const float*)d_in[8];  const float* bv = (const float*)d_in[9];
    const float* Wo = (const float*)d_in[10]; const float* bo = (const float*)d_in[11];
    const float* W1 = (const float*)d_in[12]; const float* b1 = (const float*)d_in[13];
    const float* W2 = (const float*)d_in[14]; const float* b2 = (const float*)d_in[15];
    const float* Wg = (const float*)d_in[16]; const float* bg = (const float*)d_in[17];
    float* out = (float*)d_out;

    float *q, *k, *v, *ctx, *attn, *ffnh, *ffnx, *gpre, *hbuf, *cbuf, *wT, *xr, *memr;
    int* ctr;
    cudaGetSymbolAddress((void**)&q,    g_q);
    cudaGetSymbolAddress((void**)&k,    g_k);
    cudaGetSymbolAddress((void**)&v,    g_v);
    cudaGetSymbolAddress((void**)&ctx,  g_ctx);
    cudaGetSymbolAddress((void**)&attn, g_attn);
    cudaGetSymbolAddress((void**)&ffnh, g_ffnh);
    cudaGetSymbolAddress((void**)&ffnx, g_ffnx);
    cudaGetSymbolAddress((void**)&gpre, g_gpre);
    cudaGetSymbolAddress((void**)&hbuf, g_hbuf);
    cudaGetSymbolAddress((void**)&cbuf, g_cbuf);
    cudaGetSymbolAddress((void**)&wT,   g_wT);
    cudaGetSymbolAddress((void**)&xr,   g_xr);
    cudaGetSymbolAddress((void**)&memr, g_memr);
    cudaGetSymbolAddress((void**)&ctr,  g_ctr);

    float* WqT = wT;
    float* WkT = wT + (size_t)1 * MM_;
    float* WvT = wT + (size_t)2 * MM_;
    float* WoT = wT + (size_t)3 * MM_;
    float* W1T = wT + (size_t)4 * MM_;
    float* W2T = wT + (size_t)8 * MM_;
    float* WgT = wT + (size_t)12 * MM_;
    float* WhhT = wT + (size_t)20 * MM_;

    dim3 blk(256);

    // prepass: weight transpose + tf32 round; activation rounding
    transpose_tf32<<<dim3(H_ / 32, H_ / 32), blk>>>(Wq, WqT, H_, H_);
    transpose_tf32<<<dim3(H_ / 32, H_ / 32), blk>>>(Wk, WkT, H_, H_);
    transpose_tf32<<<dim3(H_ / 32, H_ / 32), blk>>>(Wv, WvT, H_, H_);
    transpose_tf32<<<dim3(H_ / 32, H_ / 32), blk>>>(Wo, WoT, H_, H_);
    transpose_tf32<<<dim3(F_ / 32, H_ / 32), blk>>>(W1, W1T, H_, F_);
    transpose_tf32<<<dim3(H_ / 32, F_ / 32), blk>>>(W2, W2T, F_, H_);
    transpose_tf32<<<dim3(F_ / 32, (2 * H_) / 32), blk>>>(Wg, WgT, 2 * H_, F_);
    transpose_tf32<<<dim3(F_ / 32, H_ / 32), blk>>>(
        Wg + (size_t)2 * H_ * 4 * H_, WhhT, H_, F_);
    round_tf32<<<1024, blk>>>(x, xr, T_ * B_ * H_);
    round_tf32<<<1024, blk>>>(mem, memr, S_ * B_ * H_);

    const int GSM = 3 * STG_;
    cudaFuncSetAttribute(mm_gemm, cudaFuncAttributeMaxDynamicSharedMemorySize, GSM);
    cudaFuncSetAttribute(lstm_persist, cudaFuncAttributeMaxDynamicSharedMemorySize, LP_SMEM);

    // projections
    mm_gemm<<<dim3(H_ / 128, (T_ * B_) / 128), blk, GSM>>>(
        xr, xr, H_, WqT, bq, q, T_ * B_, H_, H_, 1);
    mm_gemm<<<dim3(H_ / 128, (S_ * B_) / 128), blk, GSM>>>(
        memr, memr, H_, WkT, bk, k, S_ * B_, H_, H_, 1);
    mm_gemm<<<dim3(H_ / 128, (S_ * B_) / 128), blk, GSM>>>(
        memr, memr, H_, WvT, bv, v, S_ * B_, H_, H_, 1);

    // attention
    size_t attn_smem = (size_t)ATT_SMEM_FLOATS * sizeof(float);
    cudaFuncSetAttribute(attn_kernel, cudaFuncAttributeMaxDynamicSharedMemorySize,
                         (int)attn_smem);
    attn_kernel<<<dim3(B_ * NH_, T_ / 64), blk, attn_smem>>>(q, k, v, sb, ctx);

    // output projection
    mm_gemm<<<dim3(H_ / 128, (T_ * B_) / 128), blk, GSM>>>(
        ctx, ctx, H_, WoT, bo, attn, T_ * B_, H_, H_, 1 | 8);

    // feed-forward
    mm_gemm<<<dim3(F_ / 128, (T_ * B_) / 128), blk, GSM>>>(
        xr, xr, H_, W1T, b1, ffnh, T_ * B_, F_, H_, 1 | 2 | 8);
    mm_gemm<<<dim3(H_ / 128, (T_ * B_) / 128), blk, GSM>>>(
        ffnh, ffnh, F_, W2T, b2, ffnx, T_ * B_, H_, F_, 1 | 8);

    // gate precompute (fused dual-source K=2048): gpre = [ffnx|attn] @ WgT^T + bg
    mm_gemm<<<dim3((4 * H_) / 128, (T_ * B_) / 128), blk, GSM>>>(
        ffnx, attn, H_, WgT, bg, gpre, T_ * B_, 4 * H_, 2 * H_, 1);

    // recurrence: one persistent launch
    init_state<<<(2 * B_ * H_ + 255) / 256, 256>>>(hbuf, cbuf, ctr);
    int has_tail = out_size >= T_ * B_ * H_ + 2 * B_ * H_;
    float* cf = out + (size_t)T_ * B_ * H_;
    float* hf = cf + B_ * H_;
    lstm_persist<<<128, blk, LP_SMEM>>>(gpre, WhhT, hbuf, cbuf, out, cf, hf, ctr, has_tail);
}

// round 9
// speedup vs baseline: 3.6960x; 1.1496x over previous
#include <cuda_runtime.h>
#include <math.h>
#include <stdint.h>

#define T_ 256
#define S_ 128
#define B_ 32
#define H_ 1024
#define NH_ 16
#define D_ 64
#define F_ 4096

// ---------------- scratch (static device globals; no allocation) ----------------
__device__ float g_q[(size_t)T_ * B_ * H_];
__device__ float g_k[(size_t)S_ * B_ * H_];
__device__ float g_v[(size_t)S_ * B_ * H_];
__device__ float g_ctx[(size_t)T_ * B_ * H_];
__device__ float g_attn[(size_t)T_ * B_ * H_];
__device__ float g_ffnh[(size_t)T_ * B_ * F_];
__device__ float g_ffnx[(size_t)T_ * B_ * H_];
__device__ float g_gpre[(size_t)T_ * B_ * 4 * H_];
__device__ float g_hbuf[2 * B_ * H_];
__device__ float g_cbuf[B_ * H_];
__device__ float g_xr[(size_t)T_ * B_ * H_];
__device__ float g_memr[(size_t)S_ * B_ * H_];
__device__ int   g_ctr[T_];
// transposed tf32 weights
#define MM_ (1024 * 1024)
__device__ float g_wT[(size_t)24 * MM_];

// ---------------- PTX helpers ----------------------------------------------------
__device__ __forceinline__ uint32_t smem_to_u32(const void* p) {
    uint32_t a;
    asm("{ .reg .u64 t; cvta.to.shared.u64 t, %1; cvt.u32.u64 %0, t; }" : "=r"(a) : "l"(p));
    return a;
}
__device__ __forceinline__ uint32_t f2tf32(float x) {
    uint32_t u;
    asm("cvt.rna.tf32.f32 %0, %1;" : "=r"(u) : "f"(x));
    return u;
}
__device__ __forceinline__ void cp16(uint32_t s, const void* g) {
    asm volatile("cp.async.cg.shared.global [%0], [%1], 16;\n" :: "r"(s), "l"(g));
}
__device__ __forceinline__ void cp_commit() { asm volatile("cp.async.commit_group;\n"); }
template<int N> __device__ __forceinline__ void cp_wait() {
    asm volatile("cp.async.wait_group %0;\n" :: "n"(N));
}
__device__ __forceinline__ void ldsm4(uint32_t& r0, uint32_t& r1, uint32_t& r2,
                                      uint32_t& r3, uint32_t addr) {
    asm volatile("ldmatrix.sync.aligned.m8n8.x4.shared.b16 {%0,%1,%2,%3}, [%4];"
                 : "=r"(r0), "=r"(r1), "=r"(r2), "=r"(r3) : "r"(addr));
}
__device__ __forceinline__ void mma_tf32(float (&d)[4], const uint32_t (&a)[4],
                                         uint32_t b0, uint32_t b1) {
    asm volatile(
        "mma.sync.aligned.m16n8k8.row.col.f32.tf32.tf32.f32 "
        "{%0,%1,%2,%3}, {%4,%5,%6,%7}, {%8,%9}, {%0,%1,%2,%3};\n"
        : "+f"(d[0]), "+f"(d[1]), "+f"(d[2]), "+f"(d[3])
        : "r"(a[0]), "r"(a[1]), "r"(a[2]), "r"(a[3]), "r"(b0), "r"(b1));
}
__device__ __forceinline__ float sigmoidf_(float x) { return 1.f / (1.f + __expf(-x)); }

// ---------------- prepass kernels -------------------------------------------------
__global__ __launch_bounds__(256)
void transpose_tf32(const float* __restrict__ in, float* __restrict__ out, int R, int C)
{
    __shared__ float t[32][33];
    const int bx = blockIdx.x * 32;
    const int by = blockIdx.y * 32;
    const int tx = threadIdx.x & 31;
    const int ty = threadIdx.x >> 5;
#pragma unroll
    for (int i = 0; i < 4; i++)
        t[ty + 8 * i][tx] = in[(size_t)(by + ty + 8 * i) * C + bx + tx];
    __syncthreads();
#pragma unroll
    for (int i = 0; i < 4; i++)
        out[(size_t)(bx + ty + 8 * i) * R + by + tx] =
            __uint_as_float(f2tf32(t[tx][ty + 8 * i]));
}

__global__ __launch_bounds__(256)
void round_tf32(const float* __restrict__ in, float* __restrict__ out, int n)
{
    int i = blockIdx.x * 256 + threadIdx.x;
    for (; i < n; i += gridDim.x * 256)
        out[i] = __uint_as_float(f2tf32(in[i]));
}

__global__ void init_state(float* h, float* cc, int* ctr)
{
    int i = blockIdx.x * 256 + threadIdx.x;
    if (i < 2 * B_ * H_) h[i] = 0.f;
    if (i < B_ * H_) cc[i] = 0.f;
    if (i < T_) ctr[i] = 0;
}

// ---------------- tf32 mma GEMM: C[MxN] = A @ Bt^T ---------------------------------
// A: [M][K] fp32 (already tf32-rounded), dual-source rows [A(kSplit) | A2(K-kSplit)]
// Bt: [N][K] tf32. flags: 1=bias, 2=relu, 8=round output to tf32.
#define STG_ 20480   // A 128*80 + B 128*80
__global__ __launch_bounds__(256, 2)
void mm_gemm(const float* __restrict__ A, const float* __restrict__ A2, int kSplit,
             const float* __restrict__ Bt, const float* __restrict__ bias,
             float* __restrict__ C, int M, int N, int K, int flags)
{
    extern __shared__ char smc[];
    const uint32_t sb = smem_to_u32(smc);
    const int tid = threadIdx.x, lane = tid & 31, warp = tid >> 5;
    const int wm = warp >> 2, wn = warp & 3;
    const int m0 = blockIdx.y * 128, n0 = blockIdx.x * 128;
    const int lda2 = K - kSplit;
    const int nkt = K >> 4;

    auto fill = [&](int kt) {
        const int s = kt % 3;
        const uint32_t as = sb + s * STG_;
        const uint32_t bs = as + 10240;
        const int k0 = kt << 4;
#pragma unroll
        for (int i = 0; i < 2; i++) {
            int ch = tid + 256 * i;
            int row = ch >> 2, kh = ch & 3;
            int k = k0 + kh * 4;
            const float* src = (k < kSplit)
                ? A  + (size_t)(m0 + row) * kSplit + k
                : A2 + (size_t)(m0 + row) * lda2 + (k - kSplit);
            cp16(as + row * 80 + kh * 16, src);
        }
#pragma unroll
        for (int i = 0; i < 2; i++) {
            int ch = tid + 256 * i;
            int row = ch >> 2, kh = ch & 3;
            cp16(bs + row * 80 + kh * 16, Bt + (size_t)(n0 + row) * K + k0 + kh * 4);
        }
    };

    float acc[4][4][4];
#pragma unroll
    for (int i = 0; i < 4; i++)
#pragma unroll
        for (int j = 0; j < 4; j++)
#pragma unroll
            for (int r = 0; r < 4; r++) acc[i][j][r] = 0.f;

    fill(0); cp_commit();
    if (nkt > 1) fill(1);
    cp_commit();

    const uint32_t aoff = (uint32_t)((wm * 64 + (lane & 15)) * 80 + (lane >> 4) * 16);
    const uint32_t boff = (uint32_t)((wn * 32 + (lane & 15)) * 80 + (lane >> 4) * 16);

    for (int kt = 0; kt < nkt; kt++) {
        cp_wait<1>();
        __syncthreads();
        if (kt + 2 < nkt) fill(kt + 2);
        cp_commit();
        const uint32_t as = sb + (kt % 3) * STG_;
        const uint32_t bs = as + 10240;
#pragma unroll
        for (int ks = 0; ks < 2; ks++) {
            uint32_t af[4][4], bf[2][4];
#pragma unroll
            for (int mi = 0; mi < 4; mi++)
                ldsm4(af[mi][0], af[mi][1], af[mi][2], af[mi][3],
                      as + aoff + mi * (16 * 80) + ks * 32);
#pragma unroll
            for (int nip = 0; nip < 2; nip++)
                ldsm4(bf[nip][0], bf[nip][1], bf[nip][2], bf[nip][3],
                      bs + boff + nip * (16 * 80) + ks * 32);
#pragma unroll
            for (int mi = 0; mi < 4; mi++)
#pragma unroll
                for (int ni = 0; ni < 4; ni++) {
                    const int nip = ni >> 1, o = ni & 1;
                    mma_tf32(acc[mi][ni], af[mi], bf[nip][o], bf[nip][o + 2]);
                }
        }
    }

    const int g = lane >> 2, t = lane & 3;
#pragma unroll
    for (int mi = 0; mi < 4; mi++) {
#pragma unroll
        for (int ni = 0; ni < 4; ni++) {
            const int r0 = m0 + wm * 64 + mi * 16 + g;
            const int cc = n0 + wn * 32 + ni * 8 + 2 * t;
            float2 v0 = make_float2(acc[mi][ni][0], acc[mi][ni][1]);
            float2 v1 = make_float2(acc[mi][ni][2], acc[mi][ni][3]);
            if (flags & 1) {
                float2 bb = *(const float2*)(bias + cc);
                v0.x += bb.x; v0.y += bb.y; v1.x += bb.x; v1.y += bb.y;
            }
            if (flags & 2) {
                v0.x = fmaxf(v0.x, 0.f); v0.y = fmaxf(v0.y, 0.f);
                v1.x = fmaxf(v1.x, 0.f); v1.y = fmaxf(v1.y, 0.f);
            }
            if (flags & 8) {
                v0.x = __uint_as_float(f2tf32(v0.x)); v0.y = __uint_as_float(f2tf32(v0.y));
                v1.x = __uint_as_float(f2tf32(v1.x)); v1.y = __uint_as_float(f2tf32(v1.y));
            }
            *(float2*)(C + (size_t)r0 * N + cc) = v0;
            *(float2*)(C + (size_t)(r0 + 8) * N + cc) = v1;
        }
    }
}

// ---------------- attention ---------------------------------------------------------
#define ATT_PAD 68
#define ATT_SMEM_FLOATS ((64 + 128 + 128) * ATT_PAD + 8 * 128)

__global__ __launch_bounds__(256)
void attn_kernel(const float* __restrict__ q, const float* __restrict__ k,
                 const float* __restrict__ v, const float* __restrict__ sbias,
                 float* __restrict__ ctx)
{
    extern __shared__ float sm[];
    float* Qs = sm;
    float* Ks = sm + 64 * ATT_PAD;
    float* Vs = Ks + 128 * ATT_PAD;
    float* probs = Vs + 128 * ATT_PAD;

    const int b = blockIdx.x / NH_;
    const int h = blockIdx.x % NH_;
    const int t0 = blockIdx.y * 64;
    const int tid = threadIdx.x;
    const int lane = tid & 31;
    const int warp = tid >> 5;
    const int hd = h * D_;

    for (int e = tid; e < 128 * 16; e += 256) {
        int s = e >> 4;
        int d4 = (e & 15) << 2;
        size_t gofs = ((size_t)(s * B_ + b)) * H_ + hd + d4;
        *(float4*)&Ks[s * ATT_PAD + d4] = *(const float4*)&k[gofs];
        *(float4*)&Vs[s * ATT_PAD + d4] = *(const float4*)&v[gofs];
    }
    for (int e = tid; e < 64 * 16; e += 256) {
        int r = e >> 4;
        int d4 = (e & 15) << 2;
        *(float4*)&Qs[r * ATT_PAD + d4] =
            *(const float4*)&q[((size_t)((t0 + r) * B_ + b)) * H_ + hd + d4];
    }
    __syncthreads();

    const float scale = 0.125f;
    float* pw = probs + warp * 128;

    for (int r8 = 0; r8 < 8; r8++) {
        int row = warp * 8 + r8;
        const float4* qrow = (const float4*)&Qs[row * ATT_PAD];
        const float4* k0p = (const float4*)&Ks[(lane) * ATT_PAD];
        const float4* k1p = (const float4*)&Ks[(lane + 32) * ATT_PAD];
        const float4* k2p = (const float4*)&Ks[(lane + 64) * ATT_PAD];
        const float4* k3p = (const float4*)&Ks[(lane + 96) * ATT_PAD];
        float a0 = 0.f, a1 = 0.f, a2 = 0.f, a3 = 0.f;
#pragma unroll
        for (int d4 = 0; d4 < 16; d4++) {
            float4 qv = qrow[d4];
            float4 kv;
            kv = k0p[d4]; a0 += qv.x*kv.x + qv.y*kv.y + qv.z*kv.z + qv.w*kv.w;
            kv = k1p[d4]; a1 += qv.x*kv.x + qv.y*kv.y + qv.z*kv.z + qv.w*kv.w;
            kv = k2p[d4]; a2 += qv.x*kv.x + qv.y*kv.y + qv.z*kv.z + qv.w*kv.w;
            kv = k3p[d4]; a3 += qv.x*kv.x + qv.y*kv.y + qv.z*kv.z + qv.w*kv.w;
        }
        a0 = a0 * scale + sbias[b * S_ + lane];
        a1 = a1 * scale + sbias[b * S_ + lane + 32];
        a2 = a2 * scale + sbias[b * S_ + lane + 64];
        a3 = a3 * scale + sbias[b * S_ + lane + 96];

        float mx = fmaxf(fmaxf(a0, a1), fmaxf(a2, a3));
#pragma unroll
        for (int off = 16; off; off >>= 1)
            mx = fmaxf(mx, __shfl_xor_sync(0xffffffffu, mx, off));
        float e0 = __expf(a0 - mx), e1 = __expf(a1 - mx);
        float e2 = __expf(a2 - mx), e3 = __expf(a3 - mx);
        float ssum = e0 + e1 + e2 + e3;
#pragma unroll
        for (int off = 16; off; off >>= 1)
            ssum += __shfl_xor_sync(0xffffffffu, ssum, off);
        float inv = 1.f / ssum;

        pw[lane] = e0 * inv; pw[lane + 32] = e1 * inv;
        pw[lane + 64] = e2 * inv; pw[lane + 96] = e3 * inv;
        __syncwarp();

        float c0 = 0.f, c1 = 0.f;
#pragma unroll 4
        for (int s = 0; s < 128; s++) {
            float p = pw[s];
            c0 += p * Vs[s * ATT_PAD + lane];
            c1 += p * Vs[s * ATT_PAD + lane + 32];
        }
        float* crow = &ctx[((size_t)((t0 + row) * B_ + b)) * H_ + hd];
        crow[lane] = __uint_as_float(f2tf32(c0));
        crow[lane + 32] = __uint_as_float(f2tf32(c1));
        __syncwarp();
    }
}

// ---------------- persistent LSTM recurrence ---------------------------------------
// 128 CTAs, 1/SM. CTA n owns hidden cols [n*8, n*8+8) => 32 g-cols (4 gates x 8).
// Whh slice (32 g-cols x 1024 K, tf32) resident in smem for all 256 steps.
// Per step: stream h[32x1024] as 8 tiles of 128 k-cols (16KB), 3-stage cp.async;
// warps tile (wm 2) x (wn 2) x (wk 2); smem-reduce k-halves; fused gates; grid barrier.
#define LP_BPITCH 4112
#define LP_APITCH 528
#define LP_ASTG   (32 * LP_APITCH)                  // 16896
#define LP_AOFF   131584                             // 32 * LP_BPITCH
#define LP_POFF   (LP_AOFF + 3 * LP_ASTG)            // 182272
#define LP_SMEM   (LP_POFF + 8 * 256 * 4)            // 190464

__global__ __launch_bounds__(256, 1)
void lstm_persist(const float* __restrict__ gpre, const float* __restrict__ WhhT,
                  float* __restrict__ hbuf, float* __restrict__ cbuf,
                  float* __restrict__ out, float* __restrict__ cf,
                  float* __restrict__ hf, int* __restrict__ ctr, int has_tail)
{
    extern __shared__ char smc[];
    const uint32_t sb = smem_to_u32(smc);
    const uint32_t Bs = sb;
    const uint32_t As = sb + LP_AOFF;
    float* part = (float*)(smc + LP_POFF);
    const int tid = threadIdx.x, lane = tid & 31, warp = tid >> 5;
    const int c0 = blockIdx.x * 8;

    // one-time: Whh slice -> smem. g-row (gate*8+j) maps WhhT row gate*1024+c0+j.
#pragma unroll 4
    for (int i = 0; i < 32; i++) {
        int id = tid + 256 * i;
        int row = id >> 8, ch = id & 255;
        int gate = row >> 3, j = row & 7;
        cp16(Bs + row * LP_BPITCH + ch * 16,
             WhhT + (size_t)(gate * H_ + c0 + j) * H_ + ch * 4);
    }
    cp_commit(); cp_wait<0>(); __syncthreads();

    const int wm = warp & 1, wn = (warp >> 1) & 1, wk = warp >> 2;
    const uint32_t aoff = (uint32_t)((wm * 16 + (lane & 15)) * LP_APITCH + (lane >> 4) * 16);
    const uint32_t boff = (uint32_t)((wn * 16 + (lane & 15)) * LP_BPITCH + (lane >> 4) * 16);
    const int row_e = tid >> 3, j_e = tid & 7;        // epilogue: batch row, hidden col
    const int idx_h = row_e * H_ + c0 + j_e;
    const int arow = tid >> 5, ach = tid & 31;        // A fill mapping (1024 cp16 / 256 thr)

    for (int t = 0; t < T_; t++) {
        const float* hin = hbuf + (t & 1) * (B_ * H_);
        float* hout = hbuf + (1 - (t & 1)) * (B_ * H_);
        const float* gp = gpre + (size_t)t * B_ * 4 * H_;

        // prefetch gpre + carry state (hides L2/DRAM latency behind the MMA loop)
        float gpv[4];
#pragma unroll
        for (int gi = 0; gi < 4; gi++)
            gpv[gi] = __ldg(gp + (size_t)row_e * (4 * H_) + gi * H_ + c0 + j_e);
        float cold = cbuf[idx_h];

        // A stream: 8 tiles of 128 cols; fill = 4 cp16/thread
#define LP_FILL(kt_) do { \
            const uint32_t as_f = As + ((kt_) % 3) * LP_ASTG; \
            const float* hsrc = hin + arow * H_ + (kt_) * 128 + ach * 4; \
            _Pragma("unroll") \
            for (int i_ = 0; i_ < 4; i_++) \
                cp16(as_f + (arow + 8 * i_) * LP_APITCH + ach * 16, hsrc + 8 * i_ * H_); \
        } while (0)
        // NOTE: rows split as arow + 8*i (arow 0..7), cols ach*4
        LP_FILL(0); cp_commit();
        LP_FILL(1); cp_commit();

        float acc[2][4];
#pragma unroll
        for (int i = 0; i < 2; i++)
#pragma unroll
            for (int r = 0; r < 4; r++) acc[i][r] = 0.f;

        for (int kt = 0; kt < 8; kt++) {
            cp_wait<1>();
            __syncthreads();
            if (kt + 2 < 8) LP_FILL(kt + 2);
            cp_commit();
            const uint32_t as_ = As + (kt % 3) * LP_ASTG;
            const uint32_t bk = Bs + boff + (uint32_t)kt * 512;
#pragma unroll
            for (int s8 = 0; s8 < 8; s8++) {
                const int s = wk * 8 + s8;
                uint32_t af[4], b0, b1, b2, b3;
                ldsm4(af[0], af[1], af[2], af[3], as_ + aoff + s * 32);
                ldsm4(b0, b1, b2, b3, bk + s * 32);
                mma_tf32(acc[0], af, b0, b2);
                mma_tf32(acc[1], af, b1, b3);
            }
        }

        // store per-warp partials [16x16]
        {
            const int g = lane >> 2, tq = lane & 3;
            float* pw = part + warp * 256;
#pragma unroll
            for (int ni = 0; ni < 2; ni++) {
                *(float2*)&pw[g * 16 + ni * 8 + 2 * tq] = make_float2(acc[ni][0], acc[ni][1]);
                *(float2*)&pw[(g + 8) * 16 + ni * 8 + 2 * tq] = make_float2(acc[ni][2], acc[ni][3]);
            }
        }
        __syncthreads();

        // combine k-halves + gpre; gates; state update
        {
            float gv[4];
#pragma unroll
            for (int gate = 0; gate < 4; gate++) {
                int ncol = gate * 8 + j_e;
                int w0 = (row_e >> 4) | ((ncol >> 4) << 1);
                int idx = (row_e & 15) * 16 + (ncol & 15);
                gv[gate] = part[w0 * 256 + idx] + part[(w0 + 4) * 256 + idx] + gpv[gate];
            }
            float iv = sigmoidf_(gv[0]);
            float jv = tanhf(gv[1]);
            float fv = sigmoidf_(gv[2]);
            float ov = sigmoidf_(gv[3]);
            float nc = fv * cold + iv * jv;
            float nh = ov * nc;                       // THUMT LSTMCell: activation=None
            cbuf[idx_h] = nc;
            out[(size_t)t * B_ * H_ + idx_h] = nh;
            hout[idx_h] = __uint_as_float(f2tf32(nh));
            if (has_tail && t == T_ - 1) { cf[idx_h] = nc; hf[idx_h] = nh; }
        }

        // grid barrier: arrive (atomic) + poll (volatile load)
        __threadfence();
        __syncthreads();
        if (tid == 0) {
            atomicAdd(&ctr[t], 1);
            volatile int* vc = (volatile int*)&ctr[t];
            while (*vc < 128) __nanosleep(32);
        }
        __syncthreads();
        __threadfence();
    }
}

// ---------------- launch ------------------------------------------------------------
extern "C" void kernel_launch(void* const* d_in, const int* in_sizes, int n_in,
                              void* d_out, int out_size)
{
    (void)in_sizes; (void)n_in;
    const float* x  = (const float*)d_in[0];
    const float* sb = (const float*)d_in[1];
    const float* mem = (const float*)d_in[3];
    const float* Wq = (const float*)d_in[4];  const float* bq = (const float*)d_in[5];
    const float* Wk = (const float*)d_in[6];  const float* bk = (const float*)d_in[7];
    const float* Wv = (const float*)d_in[8];  const float* bv = (const float*)d_in[9];
    const float* Wo = (const float*)d_in[10]; const float* bo = (const float*)d_in[11];
    const float* W1 = (const float*)d_in[12]; const float* b1 = (const float*)d_in[13];
    const float* W2 = (const float*)d_in[14]; const float* b2 = (const float*)d_in[15];
    const float* Wg = (const float*)d_in[16]; const float* bg = (const float*)d_in[17];
    float* out = (float*)d_out;

    float *q, *k, *v, *ctx, *attn, *ffnh, *ffnx, *gpre, *hbuf, *cbuf, *wT, *xr, *memr;
    int* ctr;
    cudaGetSymbolAddress((void**)&q,    g_q);
    cudaGetSymbolAddress((void**)&k,    g_k);
    cudaGetSymbolAddress((void**)&v,    g_v);
    cudaGetSymbolAddress((void**)&ctx,  g_ctx);
    cudaGetSymbolAddress((void**)&attn, g_attn);
    cudaGetSymbolAddress((void**)&ffnh, g_ffnh);
    cudaGetSymbolAddress((void**)&ffnx, g_ffnx);
    cudaGetSymbolAddress((void**)&gpre, g_gpre);
    cudaGetSymbolAddress((void**)&hbuf, g_hbuf);
    cudaGetSymbolAddress((void**)&cbuf, g_cbuf);
    cudaGetSymbolAddress((void**)&wT,   g_wT);
    cudaGetSymbolAddress((void**)&xr,   g_xr);
    cudaGetSymbolAddress((void**)&memr, g_memr);
    cudaGetSymbolAddress((void**)&ctr,  g_ctr);

    float* WqT = wT;
    float* WkT = wT + (size_t)1 * MM_;
    float* WvT = wT + (size_t)2 * MM_;
    float* WoT = wT + (size_t)3 * MM_;
    float* W1T = wT + (size_t)4 * MM_;
    float* W2T = wT + (size_t)8 * MM_;
    float* WgT = wT + (size_t)12 * MM_;
    float* WhhT = wT + (size_t)20 * MM_;

    dim3 blk(256);

    // prepass: weight transpose + tf32 round; activation rounding
    transpose_tf32<<<dim3(H_ / 32, H_ / 32), blk>>>(Wq, WqT, H_, H_);
    transpose_tf32<<<dim3(H_ / 32, H_ / 32), blk>>>(Wk, WkT, H_, H_);
    transpose_tf32<<<dim3(H_ / 32, H_ / 32), blk>>>(Wv, WvT, H_, H_);
    transpose_tf32<<<dim3(H_ / 32, H_ / 32), blk>>>(Wo, WoT, H_, H_);
    transpose_tf32<<<dim3(F_ / 32, H_ / 32), blk>>>(W1, W1T, H_, F_);
    transpose_tf32<<<dim3(H_ / 32, F_ / 32), blk>>>(W2, W2T, F_, H_);
    transpose_tf32<<<dim3(F_ / 32, (2 * H_) / 32), blk>>>(Wg, WgT, 2 * H_, F_);
    transpose_tf32<<<dim3(F_ / 32, H_ / 32), blk>>>(
        Wg + (size_t)2 * H_ * 4 * H_, WhhT, H_, F_);
    round_tf32<<<1024, blk>>>(x, xr, T_ * B_ * H_);
    round_tf32<<<1024, blk>>>(mem, memr, S_ * B_ * H_);

    const int GSM = 3 * STG_;
    cudaFuncSetAttribute(mm_gemm, cudaFuncAttributeMaxDynamicSharedMemorySize, GSM);
    cudaFuncSetAttribute(lstm_persist, cudaFuncAttributeMaxDynamicSharedMemorySize, LP_SMEM);

    // projections
    mm_gemm<<<dim3(H_ / 128, (T_ * B_) / 128), blk, GSM>>>(
        xr, xr, H_, WqT, bq, q, T_ * B_, H_, H_, 1);
    mm_gemm<<<dim3(H_ / 128, (S_ * B_) / 128), blk, GSM>>>(
        memr, memr, H_, WkT, bk, k, S_ * B_, H_, H_, 1);
    mm_gemm<<<dim3(H_ / 128, (S_ * B_) / 128), blk, GSM>>>(
        memr, memr, H_, WvT, bv, v, S_ * B_, H_, H_, 1);

    // attention
    size_t attn_smem = (size_t)ATT_SMEM_FLOATS * sizeof(float);
    cudaFuncSetAttribute(attn_kernel, cudaFuncAttributeMaxDynamicSharedMemorySize,
                         (int)attn_smem);
    attn_kernel<<<dim3(B_ * NH_, T_ / 64), blk, attn_smem>>>(q, k, v, sb, ctx);

    // output projection
    mm_gemm<<<dim3(H_ / 128, (T_ * B_) / 128), blk, GSM>>>(
        ctx, ctx, H_, WoT, bo, attn, T_ * B_, H_, H_, 1 | 8);

    // feed-forward
    mm_gemm<<<dim3(F_ / 128, (T_ * B_) / 128), blk, GSM>>>(
        xr, xr, H_, W1T, b1, ffnh, T_ * B_, F_, H_, 1 | 2 | 8);
    mm_gemm<<<dim3(H_ / 128, (T_ * B_) / 128), blk, GSM>>>(
        ffnh, ffnh, F_, W2T, b2, ffnx, T_ * B_, H_, F_, 1 | 8);

    // gate precompute (fused dual-source K=2048): gpre = [ffnx|attn] @ WgT^T + bg
    mm_gemm<<<dim3((4 * H_) / 128, (T_ * B_) / 128), blk, GSM>>>(
        ffnx, attn, H_, WgT, bg, gpre, T_ * B_, 4 * H_, 2 * H_, 1);

    // recurrence: one persistent launch
    init_state<<<(2 * B_ * H_ + 255) / 256, 256>>>(hbuf, cbuf, ctr);
    int has_tail = out_size >= T_ * B_ * H_ + 2 * B_ * H_;
    float* cf = out + (size_t)T_ * B_ * H_;
    float* hf = cf + B_ * H_;
    lstm_persist<<<128, blk, LP_SMEM>>>(gpre, WhhT, hbuf, cbuf, out, cf, hf, ctr, has_tail);
}